// round 1
// baseline (speedup 1.0000x reference)
#include <cuda_runtime.h>
#include <math.h>

#define BB    16
#define NT    4096
#define CH    256
#define NHEAD 8
#define DH    32
#define HID   1024
#define HH    64
#define WW2   64
#define MTOT  (BB*NT)   // 65536

// ---------------- scratch (device globals; no allocations allowed) ----------
__device__ float g_xn  [MTOT*CH];      // ln1(x), later reused for ln2(x1)
__device__ float g_xa  [MTOT*CH];      // attention input
__device__ float g_qkv [MTOT*3*CH];
__device__ float g_ctx [BB*NHEAD*DH*DH];
__device__ float g_attn[MTOT*CH];
__device__ float g_x1  [MTOT*CH];      // x after attention block
__device__ float g_x2  [MTOT*CH];      // x after FFN
__device__ float g_hid [(size_t)MTOT*HID];
__device__ float g_hid2[(size_t)MTOT*HID];
__device__ float g_pavg[BB*32*CH];
__device__ float g_pmx [BB*32*CH];
__device__ float g_avg [BB*CH];
__device__ float g_mx  [BB*CH];
__device__ float g_ca  [BB*CH];
__device__ float g_smean[MTOT];
__device__ float g_smax [MTOT];
__device__ float g_sa   [MTOT];

__device__ __forceinline__ float geluf(float x) {
    return 0.5f * x * (1.f + erff(x * 0.70710678118654752f));
}
__device__ __forceinline__ float sigmoidf_(float x) {
    return 1.f / (1.f + expf(-x));
}

// ---------------- LayerNorm over CH per row ---------------------------------
__global__ __launch_bounds__(256) void ln_kernel(
    const float* __restrict__ x, const float* __restrict__ g,
    const float* __restrict__ b, float* __restrict__ out)
{
    int m = blockIdx.x;
    int c = threadIdx.x;
    __shared__ float ssum[256], ssq[256];
    float v = x[(size_t)m*CH + c];
    ssum[c] = v; ssq[c] = v*v;
    __syncthreads();
    for (int s = 128; s > 0; s >>= 1) {
        if (c < s) { ssum[c] += ssum[c+s]; ssq[c] += ssq[c+s]; }
        __syncthreads();
    }
    float mean = ssum[0] * (1.f/CH);
    float var  = ssq[0] * (1.f/CH) - mean*mean;
    out[(size_t)m*CH + c] = (v - mean) * rsqrtf(var + 1e-5f) * g[c] + b[c];
}

// ---------------- dwconv3x3(xn) -> LN -> gelu -> + xn  => xa ----------------
__global__ __launch_bounds__(256) void attn_pre_kernel(
    const float* __restrict__ xn, const float* __restrict__ sr_w,
    const float* __restrict__ sr_b, const float* __restrict__ an_g,
    const float* __restrict__ an_b, float* __restrict__ xa)
{
    int m = blockIdx.x;
    int b = m >> 12, n = m & 4095;
    int hh = n >> 6, ww = n & 63;
    int c = threadIdx.x;
    float acc = sr_b[c];
    #pragma unroll
    for (int dy = -1; dy <= 1; dy++) {
        int y = hh + dy; if (y < 0 || y >= HH) continue;
        #pragma unroll
        for (int dx = -1; dx <= 1; dx++) {
            int xx = ww + dx; if (xx < 0 || xx >= WW2) continue;
            acc += xn[((size_t)((b<<12) + (y<<6) + xx))*CH + c] *
                   sr_w[c*9 + (dy+1)*3 + (dx+1)];
        }
    }
    __shared__ float ssum[256], ssq[256];
    ssum[c] = acc; ssq[c] = acc*acc;
    __syncthreads();
    for (int s = 128; s > 0; s >>= 1) {
        if (c < s) { ssum[c] += ssum[c+s]; ssq[c] += ssq[c+s]; }
        __syncthreads();
    }
    float mean = ssum[0] * (1.f/CH);
    float var  = ssq[0] * (1.f/CH) - mean*mean;
    float nv = (acc - mean) * rsqrtf(var + 1e-5f) * an_g[c] + an_b[c];
    xa[(size_t)m*CH + c] = xn[(size_t)m*CH + c] + geluf(nv);
}

// ---------------- generic NT GEMM: C[M,N] = A[M,K] * B[N,K]^T (+bias+adds) --
__global__ __launch_bounds__(256) void gemm_nt(
    const float* __restrict__ A, const float* __restrict__ Bw,
    float* __restrict__ Cc, int M, int N, int K,
    const float* __restrict__ bias, const float* __restrict__ add1,
    const float* __restrict__ add2)
{
    __shared__ float As[16][128];
    __shared__ float Bs[16][128];
    int bm = blockIdx.y * 128, bn = blockIdx.x * 128;
    int tid = threadIdx.x;
    int tx = tid & 15, ty = tid >> 4;
    float acc[8][8] = {};
    int lrow = tid >> 2;
    int kq   = tid & 3;
    for (int k0 = 0; k0 < K; k0 += 16) {
        #pragma unroll
        for (int i = 0; i < 2; i++) {
            int r = lrow + i*64;
            float4 a = *(const float4*)&A [(size_t)(bm+r)*K + k0 + kq*4];
            As[kq*4+0][r]=a.x; As[kq*4+1][r]=a.y; As[kq*4+2][r]=a.z; As[kq*4+3][r]=a.w;
            float4 b = *(const float4*)&Bw[(size_t)(bn+r)*K + k0 + kq*4];
            Bs[kq*4+0][r]=b.x; Bs[kq*4+1][r]=b.y; Bs[kq*4+2][r]=b.z; Bs[kq*4+3][r]=b.w;
        }
        __syncthreads();
        #pragma unroll
        for (int kk = 0; kk < 16; kk++) {
            float ar[8], br[8];
            #pragma unroll
            for (int i = 0; i < 8; i++) ar[i] = As[kk][ty*8+i];
            #pragma unroll
            for (int j = 0; j < 8; j++) br[j] = Bs[kk][tx*8+j];
            #pragma unroll
            for (int i = 0; i < 8; i++)
                #pragma unroll
                for (int j = 0; j < 8; j++)
                    acc[i][j] += ar[i]*br[j];
        }
        __syncthreads();
    }
    #pragma unroll
    for (int i = 0; i < 8; i++) {
        int r = bm + ty*8 + i;
        #pragma unroll
        for (int j = 0; j < 8; j++) {
            int cidx = bn + tx*8 + j;
            float v = acc[i][j];
            if (bias) v += bias[cidx];
            size_t idx = (size_t)r*N + cidx;
            if (add1) v += add1[idx];
            if (add2) v += add2[idx];
            Cc[idx] = v;
        }
    }
}

// ---------------- k softmax over head dim (32 contiguous) -------------------
__global__ __launch_bounds__(256) void k_softmax_kernel(float* __restrict__ qkv)
{
    int m = blockIdx.x;
    int w = threadIdx.x >> 5, lane = threadIdx.x & 31;
    size_t idx = (size_t)m*768 + 256 + w*32 + lane;
    float v = qkv[idx];
    float mx = v;
    #pragma unroll
    for (int o = 16; o > 0; o >>= 1) mx = fmaxf(mx, __shfl_xor_sync(0xffffffffu, mx, o));
    float e = expf(v - mx);
    float s = e;
    #pragma unroll
    for (int o = 16; o > 0; o >>= 1) s += __shfl_xor_sync(0xffffffffu, s, o);
    qkv[idx] = e / s;
}

// ---------------- q softmax over tokens (column softmax) --------------------
__global__ void q_softmax_kernel(float* __restrict__ qkv)
{
    int h = blockIdx.x, b = blockIdx.y;
    int d = threadIdx.x, j = threadIdx.y;          // 32 x 8
    __shared__ float red[8][32];
    __shared__ float colm[32], cols[32];
    size_t base = ((size_t)b*NT)*768 + h*32 + d;   // q section at offset 0
    float mx = -3.0e38f;
    for (int n = j; n < NT; n += 8) mx = fmaxf(mx, qkv[base + (size_t)n*768]);
    red[j][d] = mx; __syncthreads();
    if (j == 0) {
        float m2 = red[0][d];
        #pragma unroll
        for (int t = 1; t < 8; t++) m2 = fmaxf(m2, red[t][d]);
        colm[d] = m2;
    }
    __syncthreads();
    float m = colm[d];
    float s = 0.f;
    for (int n = j; n < NT; n += 8) s += expf(qkv[base + (size_t)n*768] - m);
    red[j][d] = s; __syncthreads();
    if (j == 0) {
        float s2 = 0.f;
        #pragma unroll
        for (int t = 0; t < 8; t++) s2 += red[t][d];
        cols[d] = s2;
    }
    __syncthreads();
    float inv = 1.f / cols[d];
    for (int n = j; n < NT; n += 8) {
        size_t i = base + (size_t)n*768;
        qkv[i] = expf(qkv[i] - m) * inv;
    }
}

// ---------------- ctx[b,h,d,e] = sum_n k[n,d] v[n,e] ------------------------
__global__ __launch_bounds__(1024) void ctx_kernel(
    const float* __restrict__ qkv, float* __restrict__ ctx)
{
    int bh = blockIdx.x;               // b*8+h
    int b = bh >> 3, h = bh & 7;
    __shared__ float ks[32][33];
    __shared__ float vs[32][33];
    int tid = threadIdx.x;
    int d = tid & 31, e = tid >> 5;
    int lrow = tid >> 5, lane = tid & 31;
    float acc = 0.f;
    for (int n0 = 0; n0 < NT; n0 += 32) {
        size_t rbase = ((size_t)(b*NT + n0 + lrow))*768 + h*32 + lane;
        ks[lrow][lane] = qkv[rbase + 256];
        vs[lrow][lane] = qkv[rbase + 512];
        __syncthreads();
        #pragma unroll
        for (int r = 0; r < 32; r++) acc += ks[r][d] * vs[r][e];
        __syncthreads();
    }
    ctx[((size_t)bh*32 + d)*32 + e] = acc;
}

// ---------------- attn[b,n,c=h*32+e] = sum_d q[n,h,d]*ctx[b,h,d,e] ----------
__global__ __launch_bounds__(256) void attn_apply_kernel(
    const float* __restrict__ qkv, const float* __restrict__ ctx,
    float* __restrict__ attn)
{
    int blk = blockIdx.x;              // 4096 blocks x 16 rows
    int b = blk >> 8;
    __shared__ float ctx_s[NHEAD*DH*DH];   // 8192 floats
    __shared__ float qrow[256];
    for (int i = threadIdx.x; i < NHEAD*DH*DH; i += 256)
        ctx_s[i] = ctx[(size_t)b*NHEAD*DH*DH + i];
    int c = threadIdx.x;
    int h = c >> 5, e = c & 31;
    for (int r = 0; r < 16; r++) {
        int m = blk*16 + r;
        __syncthreads();
        qrow[c] = qkv[(size_t)m*768 + c];
        __syncthreads();
        float s = 0.f;
        #pragma unroll
        for (int d2 = 0; d2 < 32; d2++)
            s += qrow[h*32 + d2] * ctx_s[(h*32 + d2)*32 + e];
        attn[(size_t)m*CH + c] = s;
    }
}

// ---------------- hidden dwconv3x3 + gelu -----------------------------------
__global__ __launch_bounds__(256) void hid_conv_kernel(
    const float* __restrict__ hid, const float* __restrict__ dw_w,
    const float* __restrict__ dw_b, float* __restrict__ hid2)
{
    int m = blockIdx.x;
    int b = m >> 12, n = m & 4095;
    int hh = n >> 6, ww = n & 63;
    for (int c = threadIdx.x; c < HID; c += 256) {
        float acc = dw_b[c];
        #pragma unroll
        for (int dy = -1; dy <= 1; dy++) {
            int y = hh + dy; if (y < 0 || y >= HH) continue;
            #pragma unroll
            for (int dx = -1; dx <= 1; dx++) {
                int xx = ww + dx; if (xx < 0 || xx >= WW2) continue;
                acc += hid[((size_t)((b<<12) + (y<<6) + xx))*HID + c] *
                       dw_w[c*9 + (dy+1)*3 + (dx+1)];
            }
        }
        hid2[(size_t)m*HID + c] = geluf(acc);
    }
}

// ---------------- CBAM: partial channel pool --------------------------------
__global__ __launch_bounds__(256) void pool_partial_kernel(
    const float* __restrict__ x2, float* __restrict__ pavg, float* __restrict__ pmx)
{
    int b = blockIdx.x, s = blockIdx.y;     // 16 x 32
    int c = threadIdx.x;
    float sum = 0.f, mx = -3.0e38f;
    for (int n = s*128; n < (s+1)*128; n++) {
        float v = x2[((size_t)(b*NT + n))*CH + c];
        sum += v; mx = fmaxf(mx, v);
    }
    pavg[(b*32 + s)*CH + c] = sum;
    pmx [(b*32 + s)*CH + c] = mx;
}

__global__ __launch_bounds__(256) void pool_final_kernel(
    const float* __restrict__ pavg, const float* __restrict__ pmx,
    float* __restrict__ avg, float* __restrict__ mx)
{
    int b = blockIdx.x;
    int c = threadIdx.x;
    float sum = 0.f, m = -3.0e38f;
    for (int s = 0; s < 32; s++) {
        sum += pavg[(b*32 + s)*CH + c];
        m = fmaxf(m, pmx[(b*32 + s)*CH + c]);
    }
    avg[b*CH + c] = sum * (1.f/NT);
    mx [b*CH + c] = m;
}

// ---------------- CBAM: channel-attention MLP -------------------------------
__global__ __launch_bounds__(256) void ca_mlp_kernel(
    const float* __restrict__ avg, const float* __restrict__ mxp,
    const float* __restrict__ w1, const float* __restrict__ w2,
    float* __restrict__ ca)
{
    int b = blockIdx.x;
    int c = threadIdx.x;
    __shared__ float sa_[256], sm_[256], t[32];
    sa_[c] = avg[b*CH + c];
    sm_[c] = mxp[b*CH + c];
    __syncthreads();
    if (c < 32) {
        int r = c & 15;
        const float* src = (c < 16) ? sa_ : sm_;
        float s = 0.f;
        for (int k = 0; k < 256; k++) s += src[k] * w1[r*256 + k];
        t[c] = fmaxf(s, 0.f);
    }
    __syncthreads();
    float s = 0.f;
    #pragma unroll
    for (int r = 0; r < 16; r++) s += (t[r] + t[16 + r]) * w2[c*16 + r];
    ca[b*CH + c] = sigmoidf_(s);
}

// ---------------- CBAM: spatial map (mean/max over channels of x2*ca) -------
__global__ __launch_bounds__(256) void smap_kernel(
    const float* __restrict__ x2, const float* __restrict__ ca,
    float* __restrict__ smean, float* __restrict__ smax)
{
    int m = blockIdx.x;
    int b = m >> 12;
    int c = threadIdx.x;
    __shared__ float ssum[256], smx[256];
    float v = x2[(size_t)m*CH + c] * ca[b*CH + c];
    ssum[c] = v; smx[c] = v;
    __syncthreads();
    for (int s = 128; s > 0; s >>= 1) {
        if (c < s) { ssum[c] += ssum[c+s]; smx[c] = fmaxf(smx[c], smx[c+s]); }
        __syncthreads();
    }
    if (c == 0) { smean[m] = ssum[0] * (1.f/CH); smax[m] = smx[0]; }
}

// ---------------- CBAM: 7x7 spatial conv + sigmoid --------------------------
__global__ __launch_bounds__(256) void sp_conv_kernel(
    const float* __restrict__ smean, const float* __restrict__ smax,
    const float* __restrict__ sp_w, const float* __restrict__ sp_b,
    float* __restrict__ sa)
{
    int m = blockIdx.x*256 + threadIdx.x;
    int b = m >> 12, n = m & 4095;
    int hh = n >> 6, ww = n & 63;
    float acc = sp_b[0];
    #pragma unroll
    for (int dy = -3; dy <= 3; dy++) {
        int y = hh + dy; if (y < 0 || y >= HH) continue;
        #pragma unroll
        for (int dx = -3; dx <= 3; dx++) {
            int xx = ww + dx; if (xx < 0 || xx >= WW2) continue;
            int idx = (b << 12) + (y << 6) + xx;
            int k = (dy+3)*7 + (dx+3);
            acc += smean[idx]*sp_w[k] + smax[idx]*sp_w[49 + k];
        }
    }
    sa[m] = sigmoidf_(acc);
}

// ---------------- final scale -----------------------------------------------
__global__ __launch_bounds__(256) void final_kernel(
    const float* __restrict__ x2, const float* __restrict__ ca,
    const float* __restrict__ sa, float* __restrict__ out)
{
    int i = blockIdx.x*256 + threadIdx.x;   // over MTOT*CH
    int m = i >> 8, c = i & 255;
    int b = m >> 12;
    out[i] = x2[i] * ca[b*CH + c] * sa[m];
}

// ---------------- launch ----------------------------------------------------
extern "C" void kernel_launch(void* const* d_in, const int* in_sizes, int n_in,
                              void* d_out, int out_size)
{
    const float* x      = (const float*)d_in[0];
    // d_in[1], d_in[2] are H, W (int32 scalars) — constants here
    const float* n1_g   = (const float*)d_in[3];
    const float* n1_b   = (const float*)d_in[4];
    const float* sr_w   = (const float*)d_in[5];
    const float* sr_b   = (const float*)d_in[6];
    const float* an_g   = (const float*)d_in[7];
    const float* an_b   = (const float*)d_in[8];
    const float* qkv_w  = (const float*)d_in[9];
    const float* proj_w = (const float*)d_in[10];
    const float* proj_b = (const float*)d_in[11];
    const float* n2_g   = (const float*)d_in[12];
    const float* n2_b   = (const float*)d_in[13];
    const float* fc1_w  = (const float*)d_in[14];
    const float* fc1_b  = (const float*)d_in[15];
    const float* dw_w   = (const float*)d_in[16];
    const float* dw_b   = (const float*)d_in[17];
    const float* fc2_w  = (const float*)d_in[18];
    const float* fc2_b  = (const float*)d_in[19];
    const float* ca_w1  = (const float*)d_in[20];
    const float* ca_w2  = (const float*)d_in[21];
    const float* sp_w   = (const float*)d_in[22];
    const float* sp_b   = (const float*)d_in[23];
    float* out = (float*)d_out;

    float *p_xn, *p_xa, *p_qkv, *p_ctx, *p_attn, *p_x1, *p_x2, *p_hid, *p_hid2;
    float *p_pavg, *p_pmx, *p_avg, *p_mx, *p_ca, *p_smean, *p_smax, *p_sa;
    cudaGetSymbolAddress((void**)&p_xn,   g_xn);
    cudaGetSymbolAddress((void**)&p_xa,   g_xa);
    cudaGetSymbolAddress((void**)&p_qkv,  g_qkv);
    cudaGetSymbolAddress((void**)&p_ctx,  g_ctx);
    cudaGetSymbolAddress((void**)&p_attn, g_attn);
    cudaGetSymbolAddress((void**)&p_x1,   g_x1);
    cudaGetSymbolAddress((void**)&p_x2,   g_x2);
    cudaGetSymbolAddress((void**)&p_hid,  g_hid);
    cudaGetSymbolAddress((void**)&p_hid2, g_hid2);
    cudaGetSymbolAddress((void**)&p_pavg, g_pavg);
    cudaGetSymbolAddress((void**)&p_pmx,  g_pmx);
    cudaGetSymbolAddress((void**)&p_avg,  g_avg);
    cudaGetSymbolAddress((void**)&p_mx,   g_mx);
    cudaGetSymbolAddress((void**)&p_ca,   g_ca);
    cudaGetSymbolAddress((void**)&p_smean,g_smean);
    cudaGetSymbolAddress((void**)&p_smax, g_smax);
    cudaGetSymbolAddress((void**)&p_sa,   g_sa);

    // ---- attention branch ----
    ln_kernel<<<MTOT, 256>>>(x, n1_g, n1_b, p_xn);
    attn_pre_kernel<<<MTOT, 256>>>(p_xn, sr_w, sr_b, an_g, an_b, p_xa);
    gemm_nt<<<dim3(768/128, MTOT/128), 256>>>(p_xa, qkv_w, p_qkv,
                                              MTOT, 768, 256, nullptr, nullptr, nullptr);
    k_softmax_kernel<<<MTOT, 256>>>(p_qkv);
    q_softmax_kernel<<<dim3(NHEAD, BB), dim3(32, 8)>>>(p_qkv);
    ctx_kernel<<<BB*NHEAD, 1024>>>(p_qkv, p_ctx);
    attn_apply_kernel<<<MTOT/16, 256>>>(p_qkv, p_ctx, p_attn);
    gemm_nt<<<dim3(256/128, MTOT/128), 256>>>(p_attn, proj_w, p_x1,
                                              MTOT, 256, 256, proj_b, p_xn, x);

    // ---- MixFFN ----
    ln_kernel<<<MTOT, 256>>>(p_x1, n2_g, n2_b, p_xn);  // reuse g_xn for ln2
    gemm_nt<<<dim3(1024/128, MTOT/128), 256>>>(p_xn, fc1_w, p_hid,
                                               MTOT, 1024, 256, fc1_b, nullptr, nullptr);
    hid_conv_kernel<<<MTOT, 256>>>(p_hid, dw_w, dw_b, p_hid2);
    gemm_nt<<<dim3(256/128, MTOT/128), 256>>>(p_hid2, fc2_w, p_x2,
                                              MTOT, 256, 1024, fc2_b, p_x1, nullptr);

    // ---- CSDA (CBAM) ----
    pool_partial_kernel<<<dim3(BB, 32), 256>>>(p_x2, p_pavg, p_pmx);
    pool_final_kernel<<<BB, 256>>>(p_pavg, p_pmx, p_avg, p_mx);
    ca_mlp_kernel<<<BB, 256>>>(p_avg, p_mx, ca_w1, ca_w2, p_ca);
    smap_kernel<<<MTOT, 256>>>(p_x2, p_ca, p_smean, p_smax);
    sp_conv_kernel<<<MTOT/256, 256>>>(p_smean, p_smax, sp_w, sp_b, p_sa);
    final_kernel<<<(MTOT*CH)/256, 256>>>(p_x2, p_ca, p_sa, out);
}

// round 4
// speedup vs baseline: 1.5031x; 1.5031x over previous
#include <cuda_runtime.h>
#include <math.h>

#define BB    16
#define NT    4096
#define CH    256
#define NHEAD 8
#define DH    32
#define HID   1024
#define HH    64
#define WW2   64
#define MTOT  (BB*NT)   // 65536

// ---------------- scratch (device globals; no allocations allowed) ----------
__device__ float g_xn  [MTOT*CH];
__device__ float g_xa  [MTOT*CH];
__device__ float g_qkv [MTOT*3*CH];
__device__ float g_ctx [BB*NHEAD*DH*DH];
__device__ float g_attn[MTOT*CH];
__device__ float g_x1  [MTOT*CH];
__device__ float g_x2  [MTOT*CH];
__device__ float g_hid [(size_t)MTOT*HID];
__device__ float g_hid2[(size_t)MTOT*HID];
__device__ float g_pavg[BB*32*CH];     // also reused as q-stat partial max
__device__ float g_pmx [BB*32*CH];     // also reused as q-stat partial sum
__device__ float g_avg [BB*CH];        // also reused as q col max
__device__ float g_mx  [BB*CH];        // also reused as q col inv-sum
__device__ float g_ca  [BB*CH];
__device__ float g_smean[MTOT];
__device__ float g_smax [MTOT];
__device__ float g_sa   [MTOT];

__device__ __forceinline__ float geluf(float x) {
    return 0.5f * x * (1.f + erff(x * 0.70710678118654752f));
}
__device__ __forceinline__ float sigmoidf_(float x) {
    return 1.f / (1.f + expf(-x));
}
__device__ __forceinline__ unsigned f2tf(float f) {
    unsigned r; asm("cvt.rna.tf32.f32 %0, %1;" : "=r"(r) : "f"(f)); return r;
}
__device__ __forceinline__ void mma8(float* c, const unsigned* a, const unsigned* b) {
    asm("mma.sync.aligned.m16n8k8.row.col.f32.tf32.tf32.f32 "
        "{%0,%1,%2,%3},{%4,%5,%6,%7},{%8,%9},{%0,%1,%2,%3};"
        : "+f"(c[0]), "+f"(c[1]), "+f"(c[2]), "+f"(c[3])
        : "r"(a[0]), "r"(a[1]), "r"(a[2]), "r"(a[3]), "r"(b[0]), "r"(b[1]));
}

// ---------------- LayerNorm over CH per row ---------------------------------
__global__ __launch_bounds__(256) void ln_kernel(
    const float* __restrict__ x, const float* __restrict__ g,
    const float* __restrict__ b, float* __restrict__ out)
{
    int m = blockIdx.x;
    int c = threadIdx.x;
    __shared__ float ssum[256], ssq[256];
    float v = x[(size_t)m*CH + c];
    ssum[c] = v; ssq[c] = v*v;
    __syncthreads();
    for (int s = 128; s > 0; s >>= 1) {
        if (c < s) { ssum[c] += ssum[c+s]; ssq[c] += ssq[c+s]; }
        __syncthreads();
    }
    float mean = ssum[0] * (1.f/CH);
    float var  = ssq[0] * (1.f/CH) - mean*mean;
    out[(size_t)m*CH + c] = (v - mean) * rsqrtf(var + 1e-5f) * g[c] + b[c];
}

// ---------------- dwconv3x3(xn) -> LN -> gelu -> + xn  => xa ----------------
__global__ __launch_bounds__(256) void attn_pre_kernel(
    const float* __restrict__ xn, const float* __restrict__ sr_w,
    const float* __restrict__ sr_b, const float* __restrict__ an_g,
    const float* __restrict__ an_b, float* __restrict__ xa)
{
    int m = blockIdx.x;
    int b = m >> 12, n = m & 4095;
    int hh = n >> 6, ww = n & 63;
    int c = threadIdx.x;
    float acc = sr_b[c];
    #pragma unroll
    for (int dy = -1; dy <= 1; dy++) {
        int y = hh + dy; if (y < 0 || y >= HH) continue;
        #pragma unroll
        for (int dx = -1; dx <= 1; dx++) {
            int xx = ww + dx; if (xx < 0 || xx >= WW2) continue;
            acc += xn[((size_t)((b<<12) + (y<<6) + xx))*CH + c] *
                   sr_w[c*9 + (dy+1)*3 + (dx+1)];
        }
    }
    __shared__ float ssum[256], ssq[256];
    ssum[c] = acc; ssq[c] = acc*acc;
    __syncthreads();
    for (int s = 128; s > 0; s >>= 1) {
        if (c < s) { ssum[c] += ssum[c+s]; ssq[c] += ssq[c+s]; }
        __syncthreads();
    }
    float mean = ssum[0] * (1.f/CH);
    float var  = ssq[0] * (1.f/CH) - mean*mean;
    float nv = (acc - mean) * rsqrtf(var + 1e-5f) * an_g[c] + an_b[c];
    xa[(size_t)m*CH + c] = xn[(size_t)m*CH + c] + geluf(nv);
}

// ---------------- tf32 tensor-core NT GEMM ---------------------------------
// C[M,N] = A[M,K] * B[N,K]^T (+bias +add1 +add2). M%128==0, N%128==0, K%32==0.
__global__ __launch_bounds__(256, 2) void gemm_tf32(
    const float* __restrict__ A, const float* __restrict__ Bw,
    float* __restrict__ Cc, int M, int N, int K,
    const float* __restrict__ bias, const float* __restrict__ add1,
    const float* __restrict__ add2)
{
    __shared__ unsigned As[32][132];
    __shared__ unsigned Bs[32][132];
    int bm = blockIdx.y * 128, bn = blockIdx.x * 128;
    int tid = threadIdx.x;
    int warp = tid >> 5, lane = tid & 31;
    int wm = (warp & 1) * 64, wn = (warp >> 1) * 32;
    int g = lane >> 2, q = lane & 3;

    float acc[4][4][4];
    #pragma unroll
    for (int i = 0; i < 4; i++)
        #pragma unroll
        for (int j = 0; j < 4; j++)
            #pragma unroll
            for (int r = 0; r < 4; r++) acc[i][j][r] = 0.f;

    int lr = tid >> 3;   // 0..31 row within 32-row slab
    int lq = tid & 7;    // 0..7 float4-chunk along k

    for (int k0 = 0; k0 < K; k0 += 32) {
        #pragma unroll
        for (int i = 0; i < 4; i++) {
            int row = lr + i*32;
            float4 a = *(const float4*)&A [(size_t)(bm+row)*K + k0 + lq*4];
            As[lq*4+0][row] = f2tf(a.x);
            As[lq*4+1][row] = f2tf(a.y);
            As[lq*4+2][row] = f2tf(a.z);
            As[lq*4+3][row] = f2tf(a.w);
            float4 b = *(const float4*)&Bw[(size_t)(bn+row)*K + k0 + lq*4];
            Bs[lq*4+0][row] = f2tf(b.x);
            Bs[lq*4+1][row] = f2tf(b.y);
            Bs[lq*4+2][row] = f2tf(b.z);
            Bs[lq*4+3][row] = f2tf(b.w);
        }
        __syncthreads();
        #pragma unroll
        for (int ks = 0; ks < 32; ks += 8) {
            unsigned af[4][4], bf[4][2];
            #pragma unroll
            for (int mt = 0; mt < 4; mt++) {
                int row = wm + mt*16 + g;
                af[mt][0] = As[ks+q  ][row];
                af[mt][1] = As[ks+q  ][row+8];
                af[mt][2] = As[ks+q+4][row];
                af[mt][3] = As[ks+q+4][row+8];
            }
            #pragma unroll
            for (int nt = 0; nt < 4; nt++) {
                int col = wn + nt*8 + g;
                bf[nt][0] = Bs[ks+q  ][col];
                bf[nt][1] = Bs[ks+q+4][col];
            }
            #pragma unroll
            for (int mt = 0; mt < 4; mt++)
                #pragma unroll
                for (int nt = 0; nt < 4; nt++)
                    mma8(acc[mt][nt], af[mt], bf[nt]);
        }
        __syncthreads();
    }

    // epilogue
    #pragma unroll
    for (int mt = 0; mt < 4; mt++) {
        #pragma unroll
        for (int half = 0; half < 2; half++) {
            int r = bm + wm + mt*16 + g + half*8;
            #pragma unroll
            for (int nt = 0; nt < 4; nt++) {
                int c0 = bn + wn + nt*8 + q*2;
                float v0 = acc[mt][nt][half*2+0];
                float v1 = acc[mt][nt][half*2+1];
                if (bias) { v0 += bias[c0]; v1 += bias[c0+1]; }
                size_t idx = (size_t)r*N + c0;
                if (add1) { float2 t = *(const float2*)&add1[idx]; v0 += t.x; v1 += t.y; }
                if (add2) { float2 t = *(const float2*)&add2[idx]; v0 += t.x; v1 += t.y; }
                float2 o; o.x = v0; o.y = v1;
                *(float2*)&Cc[idx] = o;
            }
        }
    }
}

// ---------------- q column-softmax stats: partial (online max/sum) ----------
__global__ __launch_bounds__(256) void qstat_partial_kernel(
    const float* __restrict__ qkv, float* __restrict__ pm, float* __restrict__ ps)
{
    int chunk = blockIdx.x, b = blockIdx.y;
    int c = threadIdx.x;
    float m = -3.0e38f, s = 0.f;
    size_t base = ((size_t)(b*NT + chunk*128))*768 + c;
    for (int r = 0; r < 128; r++) {
        float v = qkv[base + (size_t)r*768];
        float nm = fmaxf(m, v);
        s = s*expf(m - nm) + expf(v - nm);
        m = nm;
    }
    pm[(b*32 + chunk)*CH + c] = m;
    ps[(b*32 + chunk)*CH + c] = s;
}

__global__ __launch_bounds__(256) void qstat_final_kernel(
    const float* __restrict__ pm, const float* __restrict__ ps,
    float* __restrict__ qm, float* __restrict__ qinv)
{
    int b = blockIdx.x;
    int c = threadIdx.x;
    float M = -3.0e38f;
    for (int s = 0; s < 32; s++) M = fmaxf(M, pm[(b*32 + s)*CH + c]);
    float S = 0.f;
    for (int s = 0; s < 32; s++) S += ps[(b*32 + s)*CH + c] * expf(pm[(b*32 + s)*CH + c] - M);
    qm[b*CH + c] = M;
    qinv[b*CH + c] = 1.f / S;
}

// ---------------- ctx[b,h,d,e] = sum_n softmax_d(k)[n,d] v[n,e] -------------
__global__ __launch_bounds__(1024) void ctx_kernel(
    const float* __restrict__ qkv, float* __restrict__ ctx)
{
    int bh = blockIdx.x;               // b*8+h
    int b = bh >> 3, h = bh & 7;
    __shared__ float ks[32][33];
    __shared__ float vs[32][33];
    int tid = threadIdx.x;
    int d = tid & 31, e = tid >> 5;
    int lrow = tid >> 5, lane = tid & 31;
    float acc = 0.f;
    for (int n0 = 0; n0 < NT; n0 += 32) {
        size_t rbase = ((size_t)(b*NT + n0 + lrow))*768 + h*32 + lane;
        float kv = qkv[rbase + 256];
        // fused k softmax over head dim (warp = one row of 32)
        float mx = kv;
        #pragma unroll
        for (int o = 16; o > 0; o >>= 1) mx = fmaxf(mx, __shfl_xor_sync(0xffffffffu, mx, o));
        float ek = expf(kv - mx);
        float sk = ek;
        #pragma unroll
        for (int o = 16; o > 0; o >>= 1) sk += __shfl_xor_sync(0xffffffffu, sk, o);
        ks[lrow][lane] = ek / sk;
        vs[lrow][lane] = qkv[rbase + 512];
        __syncthreads();
        #pragma unroll
        for (int r = 0; r < 32; r++) acc += ks[r][d] * vs[r][e];
        __syncthreads();
    }
    ctx[((size_t)bh*32 + d)*32 + e] = acc;
}

// ---------------- attn[b,n,c=h*32+e] = sum_d softmaxed q * ctx --------------
__global__ __launch_bounds__(256) void attn_apply_kernel(
    const float* __restrict__ qkv, const float* __restrict__ ctx,
    const float* __restrict__ qm, const float* __restrict__ qinv,
    float* __restrict__ attn)
{
    int blk = blockIdx.x;              // 4096 blocks x 16 rows
    int b = blk >> 8;
    __shared__ float ctx_s[NHEAD*DH*DH];
    __shared__ float qrow[256];
    __shared__ float qm_s[256], qi_s[256];
    int c = threadIdx.x;
    for (int i = threadIdx.x; i < NHEAD*DH*DH; i += 256)
        ctx_s[i] = ctx[(size_t)b*NHEAD*DH*DH + i];
    qm_s[c] = qm[b*CH + c];
    qi_s[c] = qinv[b*CH + c];
    int h = c >> 5, e = c & 31;
    for (int r = 0; r < 16; r++) {
        int m = blk*16 + r;
        __syncthreads();
        qrow[c] = expf(qkv[(size_t)m*768 + c] - qm_s[c]) * qi_s[c];
        __syncthreads();
        float s = 0.f;
        #pragma unroll
        for (int d2 = 0; d2 < 32; d2++)
            s += qrow[h*32 + d2] * ctx_s[(h*32 + d2)*32 + e];
        attn[(size_t)m*CH + c] = s;
    }
}

// ---------------- hidden dwconv3x3 + gelu (float4) --------------------------
__global__ __launch_bounds__(256) void hid_conv_kernel(
    const float* __restrict__ hid, const float* __restrict__ dw_w,
    const float* __restrict__ dw_b, float* __restrict__ hid2)
{
    int m = blockIdx.x;
    int b = m >> 12, n = m & 4095;
    int hh = n >> 6, ww = n & 63;
    int c4 = threadIdx.x * 4;
    float w[4][9];
    #pragma unroll
    for (int i = 0; i < 4; i++)
        #pragma unroll
        for (int k = 0; k < 9; k++) w[i][k] = __ldg(&dw_w[(c4+i)*9 + k]);
    float4 acc = *(const float4*)&dw_b[c4];
    #pragma unroll
    for (int dy = -1; dy <= 1; dy++) {
        int y = hh + dy; if (y < 0 || y >= HH) continue;
        #pragma unroll
        for (int dx = -1; dx <= 1; dx++) {
            int xx = ww + dx; if (xx < 0 || xx >= WW2) continue;
            int k = (dy+1)*3 + (dx+1);
            float4 hv = *(const float4*)&hid[((size_t)((b<<12) + (y<<6) + xx))*HID + c4];
            acc.x += hv.x * w[0][k];
            acc.y += hv.y * w[1][k];
            acc.z += hv.z * w[2][k];
            acc.w += hv.w * w[3][k];
        }
    }
    float4 o;
    o.x = geluf(acc.x); o.y = geluf(acc.y); o.z = geluf(acc.z); o.w = geluf(acc.w);
    *(float4*)&hid2[(size_t)m*HID + c4] = o;
}

// ---------------- CBAM: partial channel pool --------------------------------
__global__ __launch_bounds__(256) void pool_partial_kernel(
    const float* __restrict__ x2, float* __restrict__ pavg, float* __restrict__ pmx)
{
    int b = blockIdx.x, s = blockIdx.y;
    int c = threadIdx.x;
    float sum = 0.f, mx = -3.0e38f;
    for (int n = s*128; n < (s+1)*128; n++) {
        float v = x2[((size_t)(b*NT + n))*CH + c];
        sum += v; mx = fmaxf(mx, v);
    }
    pavg[(b*32 + s)*CH + c] = sum;
    pmx [(b*32 + s)*CH + c] = mx;
}

__global__ __launch_bounds__(256) void pool_final_kernel(
    const float* __restrict__ pavg, const float* __restrict__ pmx,
    float* __restrict__ avg, float* __restrict__ mx)
{
    int b = blockIdx.x;
    int c = threadIdx.x;
    float sum = 0.f, m = -3.0e38f;
    for (int s = 0; s < 32; s++) {
        sum += pavg[(b*32 + s)*CH + c];
        m = fmaxf(m, pmx[(b*32 + s)*CH + c]);
    }
    avg[b*CH + c] = sum * (1.f/NT);
    mx [b*CH + c] = m;
}

// ---------------- CBAM: channel-attention MLP -------------------------------
__global__ __launch_bounds__(256) void ca_mlp_kernel(
    const float* __restrict__ avg, const float* __restrict__ mxp,
    const float* __restrict__ w1, const float* __restrict__ w2,
    float* __restrict__ ca)
{
    int b = blockIdx.x;
    int c = threadIdx.x;
    __shared__ float sa_[256], sm_[256], t[32];
    sa_[c] = avg[b*CH + c];
    sm_[c] = mxp[b*CH + c];
    __syncthreads();
    if (c < 32) {
        int r = c & 15;
        const float* src = (c < 16) ? sa_ : sm_;
        float s = 0.f;
        for (int k = 0; k < 256; k++) s += src[k] * w1[r*256 + k];
        t[c] = fmaxf(s, 0.f);
    }
    __syncthreads();
    float s = 0.f;
    #pragma unroll
    for (int r = 0; r < 16; r++) s += (t[r] + t[16 + r]) * w2[c*16 + r];
    ca[b*CH + c] = sigmoidf_(s);
}

// ---------------- CBAM: spatial map -----------------------------------------
__global__ __launch_bounds__(256) void smap_kernel(
    const float* __restrict__ x2, const float* __restrict__ ca,
    float* __restrict__ smean, float* __restrict__ smax)
{
    int m = blockIdx.x;
    int b = m >> 12;
    int c = threadIdx.x;
    __shared__ float ssum[256], smx[256];
    float v = x2[(size_t)m*CH + c] * ca[b*CH + c];
    ssum[c] = v; smx[c] = v;
    __syncthreads();
    for (int s = 128; s > 0; s >>= 1) {
        if (c < s) { ssum[c] += ssum[c+s]; smx[c] = fmaxf(smx[c], smx[c+s]); }
        __syncthreads();
    }
    if (c == 0) { smean[m] = ssum[0] * (1.f/CH); smax[m] = smx[0]; }
}

// ---------------- CBAM: 7x7 spatial conv + sigmoid --------------------------
__global__ __launch_bounds__(256) void sp_conv_kernel(
    const float* __restrict__ smean, const float* __restrict__ smax,
    const float* __restrict__ sp_w, const float* __restrict__ sp_b,
    float* __restrict__ sa)
{
    int m = blockIdx.x*256 + threadIdx.x;
    int b = m >> 12, n = m & 4095;
    int hh = n >> 6, ww = n & 63;
    float acc = sp_b[0];
    #pragma unroll
    for (int dy = -3; dy <= 3; dy++) {
        int y = hh + dy; if (y < 0 || y >= HH) continue;
        #pragma unroll
        for (int dx = -3; dx <= 3; dx++) {
            int xx = ww + dx; if (xx < 0 || xx >= WW2) continue;
            int idx = (b << 12) + (y << 6) + xx;
            int k = (dy+3)*7 + (dx+3);
            acc += smean[idx]*sp_w[k] + smax[idx]*sp_w[49 + k];
        }
    }
    sa[m] = sigmoidf_(acc);
}

// ---------------- final scale -----------------------------------------------
__global__ __launch_bounds__(256) void final_kernel(
    const float* __restrict__ x2, const float* __restrict__ ca,
    const float* __restrict__ sa, float* __restrict__ out)
{
    int i = blockIdx.x*256 + threadIdx.x;
    int m = i >> 8, c = i & 255;
    int b = m >> 12;
    out[i] = x2[i] * ca[b*CH + c] * sa[m];
}

// ---------------- launch ----------------------------------------------------
extern "C" void kernel_launch(void* const* d_in, const int* in_sizes, int n_in,
                              void* d_out, int out_size)
{
    const float* x      = (const float*)d_in[0];
    const float* n1_g   = (const float*)d_in[3];
    const float* n1_b   = (const float*)d_in[4];
    const float* sr_w   = (const float*)d_in[5];
    const float* sr_b   = (const float*)d_in[6];
    const float* an_g   = (const float*)d_in[7];
    const float* an_b   = (const float*)d_in[8];
    const float* qkv_w  = (const float*)d_in[9];
    const float* proj_w = (const float*)d_in[10];
    const float* proj_b = (const float*)d_in[11];
    const float* n2_g   = (const float*)d_in[12];
    const float* n2_b   = (const float*)d_in[13];
    const float* fc1_w  = (const float*)d_in[14];
    const float* fc1_b  = (const float*)d_in[15];
    const float* dw_w   = (const float*)d_in[16];
    const float* dw_b   = (const float*)d_in[17];
    const float* fc2_w  = (const float*)d_in[18];
    const float* fc2_b  = (const float*)d_in[19];
    const float* ca_w1  = (const float*)d_in[20];
    const float* ca_w2  = (const float*)d_in[21];
    const float* sp_w   = (const float*)d_in[22];
    const float* sp_b   = (const float*)d_in[23];
    float* out = (float*)d_out;

    float *p_xn, *p_xa, *p_qkv, *p_ctx, *p_attn, *p_x1, *p_x2, *p_hid, *p_hid2;
    float *p_pavg, *p_pmx, *p_avg, *p_mx, *p_ca, *p_smean, *p_smax, *p_sa;
    cudaGetSymbolAddress((void**)&p_xn,   g_xn);
    cudaGetSymbolAddress((void**)&p_xa,   g_xa);
    cudaGetSymbolAddress((void**)&p_qkv,  g_qkv);
    cudaGetSymbolAddress((void**)&p_ctx,  g_ctx);
    cudaGetSymbolAddress((void**)&p_attn, g_attn);
    cudaGetSymbolAddress((void**)&p_x1,   g_x1);
    cudaGetSymbolAddress((void**)&p_x2,   g_x2);
    cudaGetSymbolAddress((void**)&p_hid,  g_hid);
    cudaGetSymbolAddress((void**)&p_hid2, g_hid2);
    cudaGetSymbolAddress((void**)&p_pavg, g_pavg);
    cudaGetSymbolAddress((void**)&p_pmx,  g_pmx);
    cudaGetSymbolAddress((void**)&p_avg,  g_avg);
    cudaGetSymbolAddress((void**)&p_mx,   g_mx);
    cudaGetSymbolAddress((void**)&p_ca,   g_ca);
    cudaGetSymbolAddress((void**)&p_smean,g_smean);
    cudaGetSymbolAddress((void**)&p_smax, g_smax);
    cudaGetSymbolAddress((void**)&p_sa,   g_sa);

    // ---- attention branch ----
    ln_kernel<<<MTOT, 256>>>(x, n1_g, n1_b, p_xn);
    attn_pre_kernel<<<MTOT, 256>>>(p_xn, sr_w, sr_b, an_g, an_b, p_xa);
    gemm_tf32<<<dim3(768/128, MTOT/128), 256>>>(p_xa, qkv_w, p_qkv,
                                                MTOT, 768, 256, nullptr, nullptr, nullptr);
    qstat_partial_kernel<<<dim3(32, BB), 256>>>(p_qkv, p_pavg, p_pmx);
    qstat_final_kernel<<<BB, 256>>>(p_pavg, p_pmx, p_avg, p_mx);
    ctx_kernel<<<BB*NHEAD, 1024>>>(p_qkv, p_ctx);
    attn_apply_kernel<<<MTOT/16, 256>>>(p_qkv, p_ctx, p_avg, p_mx, p_attn);
    gemm_tf32<<<dim3(256/128, MTOT/128), 256>>>(p_attn, proj_w, p_x1,
                                                MTOT, 256, 256, proj_b, p_xn, x);

    // ---- MixFFN ----
    ln_kernel<<<MTOT, 256>>>(p_x1, n2_g, n2_b, p_xn);
    gemm_tf32<<<dim3(1024/128, MTOT/128), 256>>>(p_xn, fc1_w, p_hid,
                                                 MTOT, 1024, 256, fc1_b, nullptr, nullptr);
    hid_conv_kernel<<<MTOT, 256>>>(p_hid, dw_w, dw_b, p_hid2);
    gemm_tf32<<<dim3(256/128, MTOT/128), 256>>>(p_hid2, fc2_w, p_x2,
                                                MTOT, 256, 1024, fc2_b, p_x1, nullptr);

    // ---- CSDA (CBAM) ----
    pool_partial_kernel<<<dim3(BB, 32), 256>>>(p_x2, p_pavg, p_pmx);
    pool_final_kernel<<<BB, 256>>>(p_pavg, p_pmx, p_avg, p_mx);
    ca_mlp_kernel<<<BB, 256>>>(p_avg, p_mx, ca_w1, ca_w2, p_ca);
    smap_kernel<<<MTOT, 256>>>(p_x2, p_ca, p_smean, p_smax);
    sp_conv_kernel<<<MTOT/256, 256>>>(p_smean, p_smax, sp_w, sp_b, p_sa);
    final_kernel<<<(MTOT*CH)/256, 256>>>(p_x2, p_ca, p_sa, out);
}

// round 5
// speedup vs baseline: 2.0039x; 1.3332x over previous
#include <cuda_runtime.h>
#include <cuda_bf16.h>
#include <math.h>

#define BB    16
#define NT    4096
#define CH    256
#define NHEAD 8
#define DH    32
#define HID   1024
#define HH    64
#define WW2   64
#define MTOT  (BB*NT)   // 65536

typedef __nv_bfloat16  bf16;
typedef __nv_bfloat162 bf162;

// ---------------- scratch (device globals; no allocations allowed) ----------
__device__ float g_xn  [MTOT*CH];
__device__ bf16  g_xa  [MTOT*CH];
__device__ bf16  g_qkv [MTOT*3*CH];
__device__ float g_ctx [BB*NHEAD*DH*DH];
__device__ bf16  g_attn[MTOT*CH];
__device__ float g_x1  [MTOT*CH];
__device__ float g_x2  [MTOT*CH];
__device__ bf16  g_hid [(size_t)MTOT*HID];
__device__ bf16  g_hid2[(size_t)MTOT*HID];
__device__ float g_pavg[BB*32*CH];     // also reused as q-stat partial max
__device__ float g_pmx [BB*32*CH];     // also reused as q-stat partial sum
__device__ float g_avg [BB*CH];        // also reused as q col max
__device__ float g_mx  [BB*CH];        // also reused as q col inv-sum
__device__ float g_ca  [BB*CH];
__device__ float g_smean[MTOT];
__device__ float g_smax [MTOT];
__device__ float g_sa   [MTOT];

__device__ __forceinline__ float geluf(float x) {
    return 0.5f * x * (1.f + erff(x * 0.70710678118654752f));
}
__device__ __forceinline__ float sigmoidf_(float x) {
    return 1.f / (1.f + expf(-x));
}
__device__ __forceinline__ unsigned packbf(float x, float y) {
    bf162 t = __floats2bfloat162_rn(x, y);
    return *reinterpret_cast<unsigned*>(&t);
}
__device__ __forceinline__ void mma16(float* c, const unsigned* a, const unsigned* b) {
    asm("mma.sync.aligned.m16n8k16.row.col.f32.bf16.bf16.f32 "
        "{%0,%1,%2,%3},{%4,%5,%6,%7},{%8,%9},{%0,%1,%2,%3};"
        : "+f"(c[0]), "+f"(c[1]), "+f"(c[2]), "+f"(c[3])
        : "r"(a[0]), "r"(a[1]), "r"(a[2]), "r"(a[3]), "r"(b[0]), "r"(b[1]));
}

// ---------------- LayerNorm over CH per row ---------------------------------
__global__ __launch_bounds__(256) void ln_kernel(
    const float* __restrict__ x, const float* __restrict__ g,
    const float* __restrict__ b, float* __restrict__ out)
{
    int m = blockIdx.x;
    int c = threadIdx.x;
    __shared__ float ssum[256], ssq[256];
    float v = x[(size_t)m*CH + c];
    ssum[c] = v; ssq[c] = v*v;
    __syncthreads();
    for (int s = 128; s > 0; s >>= 1) {
        if (c < s) { ssum[c] += ssum[c+s]; ssq[c] += ssq[c+s]; }
        __syncthreads();
    }
    float mean = ssum[0] * (1.f/CH);
    float var  = ssq[0] * (1.f/CH) - mean*mean;
    out[(size_t)m*CH + c] = (v - mean) * rsqrtf(var + 1e-5f) * g[c] + b[c];
}

// ---------------- dwconv3x3(xn) -> LN -> gelu -> + xn  => xa (bf16) ---------
__global__ __launch_bounds__(256) void attn_pre_kernel(
    const float* __restrict__ xn, const float* __restrict__ sr_w,
    const float* __restrict__ sr_b, const float* __restrict__ an_g,
    const float* __restrict__ an_b, bf16* __restrict__ xa)
{
    int m = blockIdx.x;
    int b = m >> 12, n = m & 4095;
    int hh = n >> 6, ww = n & 63;
    int c = threadIdx.x;
    float acc = sr_b[c];
    #pragma unroll
    for (int dy = -1; dy <= 1; dy++) {
        int y = hh + dy; if (y < 0 || y >= HH) continue;
        #pragma unroll
        for (int dx = -1; dx <= 1; dx++) {
            int xx = ww + dx; if (xx < 0 || xx >= WW2) continue;
            acc += xn[((size_t)((b<<12) + (y<<6) + xx))*CH + c] *
                   sr_w[c*9 + (dy+1)*3 + (dx+1)];
        }
    }
    __shared__ float ssum[256], ssq[256];
    ssum[c] = acc; ssq[c] = acc*acc;
    __syncthreads();
    for (int s = 128; s > 0; s >>= 1) {
        if (c < s) { ssum[c] += ssum[c+s]; ssq[c] += ssq[c+s]; }
        __syncthreads();
    }
    float mean = ssum[0] * (1.f/CH);
    float var  = ssq[0] * (1.f/CH) - mean*mean;
    float nv = (acc - mean) * rsqrtf(var + 1e-5f) * an_g[c] + an_b[c];
    xa[(size_t)m*CH + c] = __float2bfloat16(xn[(size_t)m*CH + c] + geluf(nv));
}

// ---------------- bf16 tensor-core NT GEMM ----------------------------------
// C[M,N] = A[M,K] * B[N,K]^T (+bias +add1 +add2). M%128==0, N%128==0, K%32==0.
// TA in {float, bf16}; TO in {float, bf16}. B always float (weights).
template<typename TA, typename TO>
__global__ __launch_bounds__(256, 2) void gemm_bf(
    const TA* __restrict__ A, const float* __restrict__ Bw,
    TO* __restrict__ Cc, int M, int N, int K,
    const float* __restrict__ bias, const float* __restrict__ add1,
    const float* __restrict__ add2)
{
    __shared__ unsigned As[128][20];   // [row][packed-k 0..15], pad->20
    __shared__ unsigned Bs[128][20];
    int bm = blockIdx.y * 128, bn = blockIdx.x * 128;
    int tid = threadIdx.x;
    int warp = tid >> 5, lane = tid & 31;
    int wm = (warp & 1) * 64, wn = (warp >> 1) * 32;
    int g = lane >> 2, q = lane & 3;

    float acc[4][4][4];
    #pragma unroll
    for (int i = 0; i < 4; i++)
        #pragma unroll
        for (int j = 0; j < 4; j++)
            #pragma unroll
            for (int r = 0; r < 4; r++) acc[i][j][r] = 0.f;

    int lr = tid >> 3;   // 0..31 row slab
    int lq = tid & 7;    // 0..7 chunk of 4 k-elements

    for (int k0 = 0; k0 < K; k0 += 32) {
        #pragma unroll
        for (int i = 0; i < 4; i++) {
            int row = lr + i*32;
            unsigned p0, p1;
            if constexpr (sizeof(TA) == 4) {
                float4 a = *(const float4*)&A[(size_t)(bm+row)*K + k0 + lq*4];
                p0 = packbf(a.x, a.y); p1 = packbf(a.z, a.w);
            } else {
                uint2 u = *(const uint2*)&A[(size_t)(bm+row)*K + k0 + lq*4];
                p0 = u.x; p1 = u.y;
            }
            As[row][lq*2  ] = p0;
            As[row][lq*2+1] = p1;
            float4 b = *(const float4*)&Bw[(size_t)(bn+row)*K + k0 + lq*4];
            Bs[row][lq*2  ] = packbf(b.x, b.y);
            Bs[row][lq*2+1] = packbf(b.z, b.w);
        }
        __syncthreads();
        #pragma unroll
        for (int ks = 0; ks < 2; ks++) {
            int kb = ks*8;
            unsigned af[4][4], bfr[4][2];
            #pragma unroll
            for (int mt = 0; mt < 4; mt++) {
                int row = wm + mt*16 + g;
                af[mt][0] = As[row  ][kb+q];
                af[mt][1] = As[row+8][kb+q];
                af[mt][2] = As[row  ][kb+q+4];
                af[mt][3] = As[row+8][kb+q+4];
            }
            #pragma unroll
            for (int nt = 0; nt < 4; nt++) {
                int col = wn + nt*8 + g;
                bfr[nt][0] = Bs[col][kb+q];
                bfr[nt][1] = Bs[col][kb+q+4];
            }
            #pragma unroll
            for (int mt = 0; mt < 4; mt++)
                #pragma unroll
                for (int nt = 0; nt < 4; nt++)
                    mma16(acc[mt][nt], af[mt], bfr[nt]);
        }
        __syncthreads();
    }

    // epilogue
    #pragma unroll
    for (int mt = 0; mt < 4; mt++) {
        #pragma unroll
        for (int half = 0; half < 2; half++) {
            int r = bm + wm + mt*16 + g + half*8;
            #pragma unroll
            for (int nt = 0; nt < 4; nt++) {
                int c0 = bn + wn + nt*8 + q*2;
                float v0 = acc[mt][nt][half*2+0];
                float v1 = acc[mt][nt][half*2+1];
                if (bias) { v0 += bias[c0]; v1 += bias[c0+1]; }
                size_t idx = (size_t)r*N + c0;
                if (add1) { float2 t = *(const float2*)&add1[idx]; v0 += t.x; v1 += t.y; }
                if (add2) { float2 t = *(const float2*)&add2[idx]; v0 += t.x; v1 += t.y; }
                if constexpr (sizeof(TO) == 4) {
                    float2 o; o.x = v0; o.y = v1;
                    *(float2*)&Cc[idx] = o;
                } else {
                    bf162 o = __floats2bfloat162_rn(v0, v1);
                    *(bf162*)&Cc[idx] = o;
                }
            }
        }
    }
}

// ---------------- q column-softmax stats: partial (online max/sum) ----------
__global__ __launch_bounds__(256) void qstat_partial_kernel(
    const bf16* __restrict__ qkv, float* __restrict__ pm, float* __restrict__ ps)
{
    int chunk = blockIdx.x, b = blockIdx.y;
    int c = threadIdx.x;
    float m = -3.0e38f, s = 0.f;
    size_t base = ((size_t)(b*NT + chunk*128))*768 + c;
    for (int r = 0; r < 128; r++) {
        float v = __bfloat162float(qkv[base + (size_t)r*768]);
        float nm = fmaxf(m, v);
        s = s*expf(m - nm) + expf(v - nm);
        m = nm;
    }
    pm[(b*32 + chunk)*CH + c] = m;
    ps[(b*32 + chunk)*CH + c] = s;
}

__global__ __launch_bounds__(256) void qstat_final_kernel(
    const float* __restrict__ pm, const float* __restrict__ ps,
    float* __restrict__ qm, float* __restrict__ qinv)
{
    int b = blockIdx.x;
    int c = threadIdx.x;
    float M = -3.0e38f;
    for (int s = 0; s < 32; s++) M = fmaxf(M, pm[(b*32 + s)*CH + c]);
    float S = 0.f;
    for (int s = 0; s < 32; s++) S += ps[(b*32 + s)*CH + c] * expf(pm[(b*32 + s)*CH + c] - M);
    qm[b*CH + c] = M;
    qinv[b*CH + c] = 1.f / S;
}

// ---------------- ctx[b,h,d,e] = sum_n softmax_d(k)[n,d] v[n,e] -------------
__global__ __launch_bounds__(1024) void ctx_kernel(
    const bf16* __restrict__ qkv, float* __restrict__ ctx)
{
    int bh = blockIdx.x;               // b*8+h
    int b = bh >> 3, h = bh & 7;
    __shared__ float ks[32][33];
    __shared__ float vs[32][33];
    int tid = threadIdx.x;
    int d = tid & 31, e = tid >> 5;
    int lrow = tid >> 5, lane = tid & 31;
    float acc = 0.f;
    for (int n0 = 0; n0 < NT; n0 += 32) {
        size_t rbase = ((size_t)(b*NT + n0 + lrow))*768 + h*32 + lane;
        float kv = __bfloat162float(qkv[rbase + 256]);
        // fused k softmax over head dim (warp = one row of 32)
        float mx = kv;
        #pragma unroll
        for (int o = 16; o > 0; o >>= 1) mx = fmaxf(mx, __shfl_xor_sync(0xffffffffu, mx, o));
        float ek = expf(kv - mx);
        float sk = ek;
        #pragma unroll
        for (int o = 16; o > 0; o >>= 1) sk += __shfl_xor_sync(0xffffffffu, sk, o);
        ks[lrow][lane] = ek / sk;
        vs[lrow][lane] = __bfloat162float(qkv[rbase + 512]);
        __syncthreads();
        #pragma unroll
        for (int r = 0; r < 32; r++) acc += ks[r][d] * vs[r][e];
        __syncthreads();
    }
    ctx[((size_t)bh*32 + d)*32 + e] = acc;
}

// ---------------- attn[b,n,c=h*32+e] = sum_d softmaxed q * ctx --------------
__global__ __launch_bounds__(256) void attn_apply_kernel(
    const bf16* __restrict__ qkv, const float* __restrict__ ctx,
    const float* __restrict__ qm, const float* __restrict__ qinv,
    bf16* __restrict__ attn)
{
    int blk = blockIdx.x;              // 4096 blocks x 16 rows
    int b = blk >> 8;
    __shared__ float ctx_s[NHEAD*DH*DH];
    __shared__ float qrow[256];
    __shared__ float qm_s[256], qi_s[256];
    int c = threadIdx.x;
    for (int i = threadIdx.x; i < NHEAD*DH*DH; i += 256)
        ctx_s[i] = ctx[(size_t)b*NHEAD*DH*DH + i];
    qm_s[c] = qm[b*CH + c];
    qi_s[c] = qinv[b*CH + c];
    int h = c >> 5, e = c & 31;
    for (int r = 0; r < 16; r++) {
        int m = blk*16 + r;
        __syncthreads();
        qrow[c] = expf(__bfloat162float(qkv[(size_t)m*768 + c]) - qm_s[c]) * qi_s[c];
        __syncthreads();
        float s = 0.f;
        #pragma unroll
        for (int d2 = 0; d2 < 32; d2++)
            s += qrow[h*32 + d2] * ctx_s[(h*32 + d2)*32 + e];
        attn[(size_t)m*CH + c] = __float2bfloat16(s);
    }
}

// ---------------- hidden dwconv3x3 + gelu (bf16 in/out) ---------------------
__global__ __launch_bounds__(256) void hid_conv_kernel(
    const bf16* __restrict__ hid, const float* __restrict__ dw_w,
    const float* __restrict__ dw_b, bf16* __restrict__ hid2)
{
    int m = blockIdx.x;
    int b = m >> 12, n = m & 4095;
    int hh = n >> 6, ww = n & 63;
    int c4 = threadIdx.x * 4;
    float w[4][9];
    #pragma unroll
    for (int i = 0; i < 4; i++)
        #pragma unroll
        for (int k = 0; k < 9; k++) w[i][k] = __ldg(&dw_w[(c4+i)*9 + k]);
    float a0 = dw_b[c4+0], a1 = dw_b[c4+1], a2 = dw_b[c4+2], a3 = dw_b[c4+3];
    #pragma unroll
    for (int dy = -1; dy <= 1; dy++) {
        int y = hh + dy; if (y < 0 || y >= HH) continue;
        #pragma unroll
        for (int dx = -1; dx <= 1; dx++) {
            int xx = ww + dx; if (xx < 0 || xx >= WW2) continue;
            int k = (dy+1)*3 + (dx+1);
            uint2 u = *(const uint2*)&hid[((size_t)((b<<12) + (y<<6) + xx))*HID + c4];
            bf162 h01 = *reinterpret_cast<bf162*>(&u.x);
            bf162 h23 = *reinterpret_cast<bf162*>(&u.y);
            a0 += __bfloat162float(h01.x) * w[0][k];
            a1 += __bfloat162float(h01.y) * w[1][k];
            a2 += __bfloat162float(h23.x) * w[2][k];
            a3 += __bfloat162float(h23.y) * w[3][k];
        }
    }
    bf162 o01 = __floats2bfloat162_rn(geluf(a0), geluf(a1));
    bf162 o23 = __floats2bfloat162_rn(geluf(a2), geluf(a3));
    uint2 o; o.x = *reinterpret_cast<unsigned*>(&o01); o.y = *reinterpret_cast<unsigned*>(&o23);
    *(uint2*)&hid2[(size_t)m*HID + c4] = o;
}

// ---------------- CBAM: partial channel pool --------------------------------
__global__ __launch_bounds__(256) void pool_partial_kernel(
    const float* __restrict__ x2, float* __restrict__ pavg, float* __restrict__ pmx)
{
    int b = blockIdx.x, s = blockIdx.y;
    int c = threadIdx.x;
    float sum = 0.f, mx = -3.0e38f;
    for (int n = s*128; n < (s+1)*128; n++) {
        float v = x2[((size_t)(b*NT + n))*CH + c];
        sum += v; mx = fmaxf(mx, v);
    }
    pavg[(b*32 + s)*CH + c] = sum;
    pmx [(b*32 + s)*CH + c] = mx;
}

__global__ __launch_bounds__(256) void pool_final_kernel(
    const float* __restrict__ pavg, const float* __restrict__ pmx,
    float* __restrict__ avg, float* __restrict__ mx)
{
    int b = blockIdx.x;
    int c = threadIdx.x;
    float sum = 0.f, m = -3.0e38f;
    for (int s = 0; s < 32; s++) {
        sum += pavg[(b*32 + s)*CH + c];
        m = fmaxf(m, pmx[(b*32 + s)*CH + c]);
    }
    avg[b*CH + c] = sum * (1.f/NT);
    mx [b*CH + c] = m;
}

// ---------------- CBAM: channel-attention MLP -------------------------------
__global__ __launch_bounds__(256) void ca_mlp_kernel(
    const float* __restrict__ avg, const float* __restrict__ mxp,
    const float* __restrict__ w1, const float* __restrict__ w2,
    float* __restrict__ ca)
{
    int b = blockIdx.x;
    int c = threadIdx.x;
    __shared__ float sa_[256], sm_[256], t[32];
    sa_[c] = avg[b*CH + c];
    sm_[c] = mxp[b*CH + c];
    __syncthreads();
    if (c < 32) {
        int r = c & 15;
        const float* src = (c < 16) ? sa_ : sm_;
        float s = 0.f;
        for (int k = 0; k < 256; k++) s += src[k] * w1[r*256 + k];
        t[c] = fmaxf(s, 0.f);
    }
    __syncthreads();
    float s = 0.f;
    #pragma unroll
    for (int r = 0; r < 16; r++) s += (t[r] + t[16 + r]) * w2[c*16 + r];
    ca[b*CH + c] = sigmoidf_(s);
}

// ---------------- CBAM: spatial map -----------------------------------------
__global__ __launch_bounds__(256) void smap_kernel(
    const float* __restrict__ x2, const float* __restrict__ ca,
    float* __restrict__ smean, float* __restrict__ smax)
{
    int m = blockIdx.x;
    int b = m >> 12;
    int c = threadIdx.x;
    __shared__ float ssum[256], smx[256];
    float v = x2[(size_t)m*CH + c] * ca[b*CH + c];
    ssum[c] = v; smx[c] = v;
    __syncthreads();
    for (int s = 128; s > 0; s >>= 1) {
        if (c < s) { ssum[c] += ssum[c+s]; smx[c] = fmaxf(smx[c], smx[c+s]); }
        __syncthreads();
    }
    if (c == 0) { smean[m] = ssum[0] * (1.f/CH); smax[m] = smx[0]; }
}

// ---------------- CBAM: 7x7 spatial conv + sigmoid --------------------------
__global__ __launch_bounds__(256) void sp_conv_kernel(
    const float* __restrict__ smean, const float* __restrict__ smax,
    const float* __restrict__ sp_w, const float* __restrict__ sp_b,
    float* __restrict__ sa)
{
    int m = blockIdx.x*256 + threadIdx.x;
    int b = m >> 12, n = m & 4095;
    int hh = n >> 6, ww = n & 63;
    float acc = sp_b[0];
    #pragma unroll
    for (int dy = -3; dy <= 3; dy++) {
        int y = hh + dy; if (y < 0 || y >= HH) continue;
        #pragma unroll
        for (int dx = -3; dx <= 3; dx++) {
            int xx = ww + dx; if (xx < 0 || xx >= WW2) continue;
            int idx = (b << 12) + (y << 6) + xx;
            int k = (dy+3)*7 + (dx+3);
            acc += smean[idx]*sp_w[k] + smax[idx]*sp_w[49 + k];
        }
    }
    sa[m] = sigmoidf_(acc);
}

// ---------------- final scale -----------------------------------------------
__global__ __launch_bounds__(256) void final_kernel(
    const float* __restrict__ x2, const float* __restrict__ ca,
    const float* __restrict__ sa, float* __restrict__ out)
{
    int i = blockIdx.x*256 + threadIdx.x;
    int m = i >> 8, c = i & 255;
    int b = m >> 12;
    out[i] = x2[i] * ca[b*CH + c] * sa[m];
}

// ---------------- launch ----------------------------------------------------
extern "C" void kernel_launch(void* const* d_in, const int* in_sizes, int n_in,
                              void* d_out, int out_size)
{
    const float* x      = (const float*)d_in[0];
    const float* n1_g   = (const float*)d_in[3];
    const float* n1_b   = (const float*)d_in[4];
    const float* sr_w   = (const float*)d_in[5];
    const float* sr_b   = (const float*)d_in[6];
    const float* an_g   = (const float*)d_in[7];
    const float* an_b   = (const float*)d_in[8];
    const float* qkv_w  = (const float*)d_in[9];
    const float* proj_w = (const float*)d_in[10];
    const float* proj_b = (const float*)d_in[11];
    const float* n2_g   = (const float*)d_in[12];
    const float* n2_b   = (const float*)d_in[13];
    const float* fc1_w  = (const float*)d_in[14];
    const float* fc1_b  = (const float*)d_in[15];
    const float* dw_w   = (const float*)d_in[16];
    const float* dw_b   = (const float*)d_in[17];
    const float* fc2_w  = (const float*)d_in[18];
    const float* fc2_b  = (const float*)d_in[19];
    const float* ca_w1  = (const float*)d_in[20];
    const float* ca_w2  = (const float*)d_in[21];
    const float* sp_w   = (const float*)d_in[22];
    const float* sp_b   = (const float*)d_in[23];
    float* out = (float*)d_out;

    float *p_xn, *p_ctx, *p_x1, *p_x2;
    bf16  *p_xa, *p_qkv, *p_attn, *p_hid, *p_hid2;
    float *p_pavg, *p_pmx, *p_avg, *p_mx, *p_ca, *p_smean, *p_smax, *p_sa;
    cudaGetSymbolAddress((void**)&p_xn,   g_xn);
    cudaGetSymbolAddress((void**)&p_xa,   g_xa);
    cudaGetSymbolAddress((void**)&p_qkv,  g_qkv);
    cudaGetSymbolAddress((void**)&p_ctx,  g_ctx);
    cudaGetSymbolAddress((void**)&p_attn, g_attn);
    cudaGetSymbolAddress((void**)&p_x1,   g_x1);
    cudaGetSymbolAddress((void**)&p_x2,   g_x2);
    cudaGetSymbolAddress((void**)&p_hid,  g_hid);
    cudaGetSymbolAddress((void**)&p_hid2, g_hid2);
    cudaGetSymbolAddress((void**)&p_pavg, g_pavg);
    cudaGetSymbolAddress((void**)&p_pmx,  g_pmx);
    cudaGetSymbolAddress((void**)&p_avg,  g_avg);
    cudaGetSymbolAddress((void**)&p_mx,   g_mx);
    cudaGetSymbolAddress((void**)&p_ca,   g_ca);
    cudaGetSymbolAddress((void**)&p_smean,g_smean);
    cudaGetSymbolAddress((void**)&p_smax, g_smax);
    cudaGetSymbolAddress((void**)&p_sa,   g_sa);

    // ---- attention branch ----
    ln_kernel<<<MTOT, 256>>>(x, n1_g, n1_b, p_xn);
    attn_pre_kernel<<<MTOT, 256>>>(p_xn, sr_w, sr_b, an_g, an_b, p_xa);
    gemm_bf<bf16, bf16><<<dim3(768/128, MTOT/128), 256>>>(p_xa, qkv_w, p_qkv,
                                                MTOT, 768, 256, nullptr, nullptr, nullptr);
    qstat_partial_kernel<<<dim3(32, BB), 256>>>(p_qkv, p_pavg, p_pmx);
    qstat_final_kernel<<<BB, 256>>>(p_pavg, p_pmx, p_avg, p_mx);
    ctx_kernel<<<BB*NHEAD, 1024>>>(p_qkv, p_ctx);
    attn_apply_kernel<<<MTOT/16, 256>>>(p_qkv, p_ctx, p_avg, p_mx, p_attn);
    gemm_bf<bf16, float><<<dim3(256/128, MTOT/128), 256>>>(p_attn, proj_w, p_x1,
                                                MTOT, 256, 256, proj_b, p_xn, x);

    // ---- MixFFN ----
    ln_kernel<<<MTOT, 256>>>(p_x1, n2_g, n2_b, p_xn);
    gemm_bf<float, bf16><<<dim3(1024/128, MTOT/128), 256>>>(p_xn, fc1_w, p_hid,
                                                 MTOT, 1024, 256, fc1_b, nullptr, nullptr);
    hid_conv_kernel<<<MTOT, 256>>>(p_hid, dw_w, dw_b, p_hid2);
    gemm_bf<bf16, float><<<dim3(256/128, MTOT/128), 256>>>(p_hid2, fc2_w, p_x2,
                                                MTOT, 256, 1024, fc2_b, p_x1, nullptr);

    // ---- CSDA (CBAM) ----
    pool_partial_kernel<<<dim3(BB, 32), 256>>>(p_x2, p_pavg, p_pmx);
    pool_final_kernel<<<BB, 256>>>(p_pavg, p_pmx, p_avg, p_mx);
    ca_mlp_kernel<<<BB, 256>>>(p_avg, p_mx, ca_w1, ca_w2, p_ca);
    smap_kernel<<<MTOT, 256>>>(p_x2, p_ca, p_smean, p_smax);
    sp_conv_kernel<<<MTOT/256, 256>>>(p_smean, p_smax, sp_w, sp_b, p_sa);
    final_kernel<<<(MTOT*CH)/256, 256>>>(p_x2, p_ca, p_sa, out);
}

// round 14
// speedup vs baseline: 2.8283x; 1.4114x over previous
#include <cuda_runtime.h>
#include <cuda_bf16.h>
#include <math.h>

#define BB    16
#define NT    4096
#define CH    256
#define NHEAD 8
#define DH    32
#define HID   1024
#define HH    64
#define WW2   64
#define MTOT  (BB*NT)   // 65536

typedef __nv_bfloat16  bf16;
typedef __nv_bfloat162 bf162;

// ---------------- scratch ----------------------------------------------------
__device__ float g_xn  [MTOT*CH];            // ln1 output (fp32, feeds residual)
__device__ bf16  g_xa  [MTOT*CH];            // attn input; later ln2 output
__device__ bf16  g_qkv [MTOT*3*CH];
__device__ float g_ctx [BB*NHEAD*DH*DH];
__device__ float g_ctxp[4*BB*NHEAD*DH*DH];
__device__ bf16  g_attn[MTOT*CH];
__device__ float g_x1  [MTOT*CH];
__device__ float g_x2  [MTOT*CH];
__device__ bf16  g_hid [(size_t)MTOT*HID];
__device__ bf16  g_hid2[(size_t)MTOT*HID];
__device__ float g_pavg[BB*64*CH];           // q-stat / pool partials
__device__ float g_pmx [BB*64*CH];
__device__ float g_avg [BB*CH];
__device__ float g_mx  [BB*CH];
__device__ float g_ca  [BB*CH];
__device__ float g_smean[MTOT];
__device__ float g_smax [MTOT];
__device__ float g_sa   [MTOT];

__device__ __forceinline__ float geluf(float x) {
    return 0.5f * x * (1.f + erff(x * 0.70710678118654752f));
}
__device__ __forceinline__ float sigmoidf_(float x) {
    return 1.f / (1.f + expf(-x));
}
__device__ __forceinline__ unsigned packbf(float x, float y) {
    bf162 t = __floats2bfloat162_rn(x, y);
    return *reinterpret_cast<unsigned*>(&t);
}
__device__ __forceinline__ void mma16(float* c, const unsigned* a, const unsigned* b) {
    asm("mma.sync.aligned.m16n8k16.row.col.f32.bf16.bf16.f32 "
        "{%0,%1,%2,%3},{%4,%5,%6,%7},{%8,%9},{%0,%1,%2,%3};"
        : "+f"(c[0]), "+f"(c[1]), "+f"(c[2]), "+f"(c[3])
        : "r"(a[0]), "r"(a[1]), "r"(a[2]), "r"(a[3]), "r"(b[0]), "r"(b[1]));
}
// block reduce (256 thr): sum of two values via shuffle + 1 sync
__device__ __forceinline__ void blk_reduce2(float& s, float& sq, float* ws, float* wq) {
    #pragma unroll
    for (int o = 16; o > 0; o >>= 1) {
        s  += __shfl_xor_sync(0xffffffffu, s,  o);
        sq += __shfl_xor_sync(0xffffffffu, sq, o);
    }
    int warp = threadIdx.x >> 5, lane = threadIdx.x & 31;
    if (lane == 0) { ws[warp] = s; wq[warp] = sq; }
    __syncthreads();
    float ts = 0.f, tq = 0.f;
    #pragma unroll
    for (int i = 0; i < 8; i++) { ts += ws[i]; tq += wq[i]; }
    s = ts; sq = tq;
}

// ---------------- LayerNorm over CH per row (templated output) ---------------
template<typename TO>
__global__ __launch_bounds__(256) void ln_kernel(
    const float* __restrict__ x, const float* __restrict__ g,
    const float* __restrict__ b, TO* __restrict__ out)
{
    int m = blockIdx.x;
    int c = threadIdx.x;
    __shared__ float ws[8], wq[8];
    float v = x[(size_t)m*CH + c];
    float s = v, sq = v*v;
    blk_reduce2(s, sq, ws, wq);
    float mean = s * (1.f/CH);
    float var  = sq * (1.f/CH) - mean*mean;
    float r = (v - mean) * rsqrtf(var + 1e-5f) * g[c] + b[c];
    if constexpr (sizeof(TO) == 4) out[(size_t)m*CH + c] = r;
    else                           out[(size_t)m*CH + c] = __float2bfloat16(r);
}

// ---------------- dwconv3x3(xn) -> LN -> gelu -> + xn  => xa (bf16) ---------
__global__ __launch_bounds__(256) void attn_pre_kernel(
    const float* __restrict__ xn, const float* __restrict__ sr_w,
    const float* __restrict__ sr_b, const float* __restrict__ an_g,
    const float* __restrict__ an_b, bf16* __restrict__ xa)
{
    int m = blockIdx.x;
    int b = m >> 12, n = m & 4095;
    int hh = n >> 6, ww = n & 63;
    int c = threadIdx.x;
    __shared__ float ws[8], wq[8];
    float acc = sr_b[c];
    #pragma unroll
    for (int dy = -1; dy <= 1; dy++) {
        int y = hh + dy; if (y < 0 || y >= HH) continue;
        #pragma unroll
        for (int dx = -1; dx <= 1; dx++) {
            int xx = ww + dx; if (xx < 0 || xx >= WW2) continue;
            acc += xn[((size_t)((b<<12) + (y<<6) + xx))*CH + c] *
                   sr_w[c*9 + (dy+1)*3 + (dx+1)];
        }
    }
    float s = acc, sq = acc*acc;
    blk_reduce2(s, sq, ws, wq);
    float mean = s * (1.f/CH);
    float var  = sq * (1.f/CH) - mean*mean;
    float nv = (acc - mean) * rsqrtf(var + 1e-5f) * an_g[c] + an_b[c];
    xa[(size_t)m*CH + c] = __float2bfloat16(xn[(size_t)m*CH + c] + geluf(nv));
}

// ---------------- bf16 tensor-core NT GEMM, register-prefetch pipelined ------
// C[M,N] = A[M,K] * B[N,K]^T (+bias +add1 +add2). M%128==0, N%128==0, K%32==0.
template<typename TA, typename TO>
__global__ __launch_bounds__(256, 2) void gemm_bf(
    const TA* __restrict__ A, const float* __restrict__ Bw,
    TO* __restrict__ Cc, int M, int N, int K,
    const float* __restrict__ bias, const float* __restrict__ add1,
    const float* __restrict__ add2)
{
    __shared__ unsigned As[128][20];   // [row][packed-k pair], pad->20
    __shared__ unsigned Bs[128][20];
    int bm = blockIdx.y * 128, bn = blockIdx.x * 128;
    int tid = threadIdx.x;
    int warp = tid >> 5, lane = tid & 31;
    int wm = (warp & 1) * 64, wn = (warp >> 1) * 32;
    int g = lane >> 2, q = lane & 3;

    float acc[4][4][4];
    #pragma unroll
    for (int i = 0; i < 4; i++)
        #pragma unroll
        for (int j = 0; j < 4; j++)
            #pragma unroll
            for (int r = 0; r < 4; r++) acc[i][j][r] = 0.f;

    int lr = tid >> 3;   // 0..31 row slab
    int lq = tid & 7;    // 0..7 chunk of 4 k-elements

    unsigned pa[4][2], pb[4][2];
#define LOAD_TILE(K0)                                                          \
    _Pragma("unroll")                                                          \
    for (int i = 0; i < 4; i++) {                                              \
        int row = lr + i*32;                                                   \
        if constexpr (sizeof(TA) == 4) {                                       \
            float4 a = *(const float4*)&A[(size_t)(bm+row)*K + (K0) + lq*4];   \
            pa[i][0] = packbf(a.x, a.y); pa[i][1] = packbf(a.z, a.w);          \
        } else {                                                               \
            uint2 u = *(const uint2*)&A[(size_t)(bm+row)*K + (K0) + lq*4];     \
            pa[i][0] = u.x; pa[i][1] = u.y;                                    \
        }                                                                      \
        float4 b = *(const float4*)&Bw[(size_t)(bn+row)*K + (K0) + lq*4];      \
        pb[i][0] = packbf(b.x, b.y); pb[i][1] = packbf(b.z, b.w);              \
    }

    LOAD_TILE(0)
    for (int k0 = 0; k0 < K; k0 += 32) {
        #pragma unroll
        for (int i = 0; i < 4; i++) {
            int row = lr + i*32;
            As[row][lq*2  ] = pa[i][0];
            As[row][lq*2+1] = pa[i][1];
            Bs[row][lq*2  ] = pb[i][0];
            Bs[row][lq*2+1] = pb[i][1];
        }
        __syncthreads();
        if (k0 + 32 < K) { LOAD_TILE(k0 + 32) }
        #pragma unroll
        for (int ks = 0; ks < 2; ks++) {
            int kb = ks*8;
            unsigned af[4][4], bfr[4][2];
            #pragma unroll
            for (int mt = 0; mt < 4; mt++) {
                int row = wm + mt*16 + g;
                af[mt][0] = As[row  ][kb+q];
                af[mt][1] = As[row+8][kb+q];
                af[mt][2] = As[row  ][kb+q+4];
                af[mt][3] = As[row+8][kb+q+4];
            }
            #pragma unroll
            for (int nt = 0; nt < 4; nt++) {
                int col = wn + nt*8 + g;
                bfr[nt][0] = Bs[col][kb+q];
                bfr[nt][1] = Bs[col][kb+q+4];
            }
            #pragma unroll
            for (int mt = 0; mt < 4; mt++)
                #pragma unroll
                for (int nt = 0; nt < 4; nt++)
                    mma16(acc[mt][nt], af[mt], bfr[nt]);
        }
        __syncthreads();
    }
#undef LOAD_TILE

    #pragma unroll
    for (int mt = 0; mt < 4; mt++) {
        #pragma unroll
        for (int half = 0; half < 2; half++) {
            int r = bm + wm + mt*16 + g + half*8;
            #pragma unroll
            for (int nt = 0; nt < 4; nt++) {
                int c0 = bn + wn + nt*8 + q*2;
                float v0 = acc[mt][nt][half*2+0];
                float v1 = acc[mt][nt][half*2+1];
                if (bias) { v0 += bias[c0]; v1 += bias[c0+1]; }
                size_t idx = (size_t)r*N + c0;
                if (add1) { float2 t = *(const float2*)&add1[idx]; v0 += t.x; v1 += t.y; }
                if (add2) { float2 t = *(const float2*)&add2[idx]; v0 += t.x; v1 += t.y; }
                if constexpr (sizeof(TO) == 4) {
                    float2 o; o.x = v0; o.y = v1;
                    *(float2*)&Cc[idx] = o;
                } else {
                    bf162 o = __floats2bfloat162_rn(v0, v1);
                    *(bf162*)&Cc[idx] = o;
                }
            }
        }
    }
}

// ---------------- q column-softmax stats: partial (64 chunks of 64 rows) -----
__global__ __launch_bounds__(256) void qstat_partial_kernel(
    const bf16* __restrict__ qkv, float* __restrict__ pm, float* __restrict__ ps)
{
    int chunk = blockIdx.x, b = blockIdx.y;
    int c = threadIdx.x;
    float m = -3.0e38f, s = 0.f;
    size_t base = ((size_t)(b*NT + chunk*64))*768 + c;
    for (int r = 0; r < 64; r++) {
        float v = __bfloat162float(qkv[base + (size_t)r*768]);
        float nm = fmaxf(m, v);
        s = s*expf(m - nm) + expf(v - nm);
        m = nm;
    }
    pm[(b*64 + chunk)*CH + c] = m;
    ps[(b*64 + chunk)*CH + c] = s;
}

__global__ __launch_bounds__(256) void qstat_final_kernel(
    const float* __restrict__ pm, const float* __restrict__ ps,
    float* __restrict__ qm, float* __restrict__ qinv)
{
    int b = blockIdx.x;
    int c = threadIdx.x;
    float M = -3.0e38f;
    for (int s = 0; s < 64; s++) M = fmaxf(M, pm[(b*64 + s)*CH + c]);
    float S = 0.f;
    for (int s = 0; s < 64; s++) S += ps[(b*64 + s)*CH + c] * expf(pm[(b*64 + s)*CH + c] - M);
    qm[b*CH + c] = M;
    qinv[b*CH + c] = 1.f / S;
}

// ---------------- ctx partial: 4-way split over tokens -----------------------
__global__ __launch_bounds__(1024) void ctx_kernel(
    const bf16* __restrict__ qkv, float* __restrict__ ctxp)
{
    int bh = blockIdx.x;               // b*8+h
    int split = blockIdx.y;            // 0..3
    int b = bh >> 3, h = bh & 7;
    __shared__ float ks[32][33];
    __shared__ float vs[32][33];
    int tid = threadIdx.x;
    int d = tid & 31, e = tid >> 5;
    int lrow = tid >> 5, lane = tid & 31;
    float acc = 0.f;
    for (int n0 = split*1024; n0 < (split+1)*1024; n0 += 32) {
        size_t rbase = ((size_t)(b*NT + n0 + lrow))*768 + h*32 + lane;
        float kv = __bfloat162float(qkv[rbase + 256]);
        float mx = kv;
        #pragma unroll
        for (int o = 16; o > 0; o >>= 1) mx = fmaxf(mx, __shfl_xor_sync(0xffffffffu, mx, o));
        float ek = expf(kv - mx);
        float sk = ek;
        #pragma unroll
        for (int o = 16; o > 0; o >>= 1) sk += __shfl_xor_sync(0xffffffffu, sk, o);
        ks[lrow][lane] = ek / sk;
        vs[lrow][lane] = __bfloat162float(qkv[rbase + 512]);
        __syncthreads();
        #pragma unroll
        for (int r = 0; r < 32; r++) acc += ks[r][d] * vs[r][e];
        __syncthreads();
    }
    ctxp[((size_t)split*BB*NHEAD + bh)*1024 + d*32 + e] = acc;
}

__global__ __launch_bounds__(256) void ctx_combine_kernel(
    const float* __restrict__ ctxp, float* __restrict__ ctx)
{
    int i = blockIdx.x*256 + threadIdx.x;   // BB*NHEAD*1024 elems
    const int STRIDE = BB*NHEAD*1024;
    ctx[i] = ctxp[i] + ctxp[STRIDE + i] + ctxp[2*STRIDE + i] + ctxp[3*STRIDE + i];
}

// ---------------- attn[b,n,c=h*32+e] = sum_d softmaxed q * ctx ---------------
__global__ __launch_bounds__(256) void attn_apply_kernel(
    const bf16* __restrict__ qkv, const float* __restrict__ ctx,
    const float* __restrict__ qm, const float* __restrict__ qinv,
    bf16* __restrict__ attn)
{
    int blk = blockIdx.x;              // 4096 blocks x 16 rows
    int b = blk >> 8;
    __shared__ float ctx_s[NHEAD*DH*DH];
    __shared__ float qrow[256];
    __shared__ float qm_s[256], qi_s[256];
    int c = threadIdx.x;
    for (int i = threadIdx.x; i < NHEAD*DH*DH; i += 256)
        ctx_s[i] = ctx[(size_t)b*NHEAD*DH*DH + i];
    qm_s[c] = qm[b*CH + c];
    qi_s[c] = qinv[b*CH + c];
    int h = c >> 5, e = c & 31;
    for (int r = 0; r < 16; r++) {
        int m = blk*16 + r;
        __syncthreads();
        qrow[c] = expf(__bfloat162float(qkv[(size_t)m*768 + c]) - qm_s[c]) * qi_s[c];
        __syncthreads();
        float s = 0.f;
        #pragma unroll
        for (int d2 = 0; d2 < 32; d2++)
            s += qrow[h*32 + d2] * ctx_s[(h*32 + d2)*32 + e];
        attn[(size_t)m*CH + c] = __float2bfloat16(s);
    }
}

// ---------------- hidden dwconv3x3 + gelu: rolling-window over x -------------
__global__ __launch_bounds__(256) void hid_conv_kernel(
    const bf16* __restrict__ hid, const float* __restrict__ dw_w,
    const float* __restrict__ dw_b, bf16* __restrict__ hid2)
{
    int blk = blockIdx.x;              // b*64 + y
    int b = blk >> 6, y = blk & 63;
    int c4 = threadIdx.x * 4;
    float w[4][9];
    #pragma unroll
    for (int i = 0; i < 4; i++)
        #pragma unroll
        for (int k = 0; k < 9; k++) w[i][k] = __ldg(&dw_w[(c4+i)*9 + k]);
    float bs0 = dw_b[c4+0], bs1 = dw_b[c4+1], bs2 = dw_b[c4+2], bs3 = dw_b[c4+3];

    float win[3][3][4];                // [col: 0=x-1,1=x,2=x+1][row][ch]
    #pragma unroll
    for (int cc = 0; cc < 3; cc++)
        #pragma unroll
        for (int r = 0; r < 3; r++)
            #pragma unroll
            for (int ch = 0; ch < 4; ch++) win[cc][r][ch] = 0.f;

    // load column x=0 into win[1]
    #pragma unroll
    for (int r = 0; r < 3; r++) {
        int yy = y - 1 + r;
        if (yy >= 0 && yy < HH) {
            uint2 u = *(const uint2*)&hid[((size_t)((b<<12) + (yy<<6)))*HID + c4];
            bf162 h01 = *reinterpret_cast<bf162*>(&u.x);
            bf162 h23 = *reinterpret_cast<bf162*>(&u.y);
            win[1][r][0] = __bfloat162float(h01.x); win[1][r][1] = __bfloat162float(h01.y);
            win[1][r][2] = __bfloat162float(h23.x); win[1][r][3] = __bfloat162float(h23.y);
        }
    }
    for (int x = 0; x < 64; x++) {
        #pragma unroll
        for (int r = 0; r < 3; r++) {
            int yy = y - 1 + r;
            if (x + 1 < 64 && yy >= 0 && yy < HH) {
                uint2 u = *(const uint2*)&hid[((size_t)((b<<12) + (yy<<6) + x + 1))*HID + c4];
                bf162 h01 = *reinterpret_cast<bf162*>(&u.x);
                bf162 h23 = *reinterpret_cast<bf162*>(&u.y);
                win[2][r][0] = __bfloat162float(h01.x); win[2][r][1] = __bfloat162float(h01.y);
                win[2][r][2] = __bfloat162float(h23.x); win[2][r][3] = __bfloat162float(h23.y);
            } else {
                win[2][r][0] = win[2][r][1] = win[2][r][2] = win[2][r][3] = 0.f;
            }
        }
        float a0 = bs0, a1 = bs1, a2 = bs2, a3 = bs3;
        #pragma unroll
        for (int r = 0; r < 3; r++)
            #pragma unroll
            for (int col = 0; col < 3; col++) {
                float w0 = w[0][r*3+col], w1 = w[1][r*3+col];
                float w2 = w[2][r*3+col], w3 = w[3][r*3+col];
                a0 += win[col][r][0]*w0;
                a1 += win[col][r][1]*w1;
                a2 += win[col][r][2]*w2;
                a3 += win[col][r][3]*w3;
            }
        bf162 o01 = __floats2bfloat162_rn(geluf(a0), geluf(a1));
        bf162 o23 = __floats2bfloat162_rn(geluf(a2), geluf(a3));
        uint2 o; o.x = *reinterpret_cast<unsigned*>(&o01); o.y = *reinterpret_cast<unsigned*>(&o23);
        *(uint2*)&hid2[((size_t)((b<<12) + (y<<6) + x))*HID + c4] = o;
        #pragma unroll
        for (int r = 0; r < 3; r++)
            #pragma unroll
            for (int ch = 0; ch < 4; ch++) {
                win[0][r][ch] = win[1][r][ch];
                win[1][r][ch] = win[2][r][ch];
            }
    }
}

// ---------------- CBAM: partial channel pool (64 chunks of 64 tokens) --------
__global__ __launch_bounds__(256) void pool_partial_kernel(
    const float* __restrict__ x2, float* __restrict__ pavg, float* __restrict__ pmx)
{
    int b = blockIdx.x, s = blockIdx.y;
    int c = threadIdx.x;
    float sum = 0.f, mx = -3.0e38f;
    for (int n = s*64; n < (s+1)*64; n++) {
        float v = x2[((size_t)(b*NT + n))*CH + c];
        sum += v; mx = fmaxf(mx, v);
    }
    pavg[(b*64 + s)*CH + c] = sum;
    pmx [(b*64 + s)*CH + c] = mx;
}

__global__ __launch_bounds__(256) void pool_final_kernel(
    const float* __restrict__ pavg, const float* __restrict__ pmx,
    float* __restrict__ avg, float* __restrict__ mx)
{
    int b = blockIdx.x;
    int c = threadIdx.x;
    float sum = 0.f, m = -3.0e38f;
    for (int s = 0; s < 64; s++) {
        sum += pavg[(b*64 + s)*CH + c];
        m = fmaxf(m, pmx[(b*64 + s)*CH + c]);
    }
    avg[b*CH + c] = sum * (1.f/NT);
    mx [b*CH + c] = m;
}

// ---------------- CBAM: channel-attention MLP --------------------------------
__global__ __launch_bounds__(256) void ca_mlp_kernel(
    const float* __restrict__ avg, const float* __restrict__ mxp,
    const float* __restrict__ w1, const float* __restrict__ w2,
    float* __restrict__ ca)
{
    int b = blockIdx.x;
    int c = threadIdx.x;
    __shared__ float sa_[256], sm_[256], t[32];
    sa_[c] = avg[b*CH + c];
    sm_[c] = mxp[b*CH + c];
    __syncthreads();
    if (c < 32) {
        int r = c & 15;
        const float* src = (c < 16) ? sa_ : sm_;
        float s = 0.f;
        for (int k = 0; k < 256; k++) s += src[k] * w1[r*256 + k];
        t[c] = fmaxf(s, 0.f);
    }
    __syncthreads();
    float s = 0.f;
    #pragma unroll
    for (int r = 0; r < 16; r++) s += (t[r] + t[16 + r]) * w2[c*16 + r];
    ca[b*CH + c] = sigmoidf_(s);
}

// ---------------- CBAM: spatial map ------------------------------------------
__global__ __launch_bounds__(256) void smap_kernel(
    const float* __restrict__ x2, const float* __restrict__ ca,
    float* __restrict__ smean, float* __restrict__ smax)
{
    int m = blockIdx.x;
    int b = m >> 12;
    int c = threadIdx.x;
    __shared__ float ws[8], wq[8];
    float v = x2[(size_t)m*CH + c] * ca[b*CH + c];
    float s = v;
    float mxv = v;
    #pragma unroll
    for (int o = 16; o > 0; o >>= 1) {
        s   += __shfl_xor_sync(0xffffffffu, s, o);
        mxv  = fmaxf(mxv, __shfl_xor_sync(0xffffffffu, mxv, o));
    }
    int warp = threadIdx.x >> 5, lane = threadIdx.x & 31;
    if (lane == 0) { ws[warp] = s; wq[warp] = mxv; }
    __syncthreads();
    if (threadIdx.x == 0) {
        float ts = 0.f, tm = -3.0e38f;
        #pragma unroll
        for (int i = 0; i < 8; i++) { ts += ws[i]; tm = fmaxf(tm, wq[i]); }
        smean[m] = ts * (1.f/CH); smax[m] = tm;
    }
}

// ---------------- CBAM: 7x7 spatial conv + sigmoid ---------------------------
__global__ __launch_bounds__(256) void sp_conv_kernel(
    const float* __restrict__ smean, const float* __restrict__ smax,
    const float* __restrict__ sp_w, const float* __restrict__ sp_b,
    float* __restrict__ sa)
{
    int m = blockIdx.x*256 + threadIdx.x;
    int b = m >> 12, n = m & 4095;
    int hh = n >> 6, ww = n & 63;
    float acc = sp_b[0];
    #pragma unroll
    for (int dy = -3; dy <= 3; dy++) {
        int y = hh + dy; if (y < 0 || y >= HH) continue;
        #pragma unroll
        for (int dx = -3; dx <= 3; dx++) {
            int xx = ww + dx; if (xx < 0 || xx >= WW2) continue;
            int idx = (b << 12) + (y << 6) + xx;
            int k = (dy+3)*7 + (dx+3);
            acc += smean[idx]*sp_w[k] + smax[idx]*sp_w[49 + k];
        }
    }
    sa[m] = sigmoidf_(acc);
}

// ---------------- final scale ------------------------------------------------
__global__ __launch_bounds__(256) void final_kernel(
    const float* __restrict__ x2, const float* __restrict__ ca,
    const float* __restrict__ sa, float* __restrict__ out)
{
    int i = blockIdx.x*256 + threadIdx.x;
    int m = i >> 8, c = i & 255;
    int b = m >> 12;
    out[i] = x2[i] * ca[b*CH + c] * sa[m];
}

// ---------------- launch -----------------------------------------------------
extern "C" void kernel_launch(void* const* d_in, const int* in_sizes, int n_in,
                              void* d_out, int out_size)
{
    const float* x      = (const float*)d_in[0];
    const float* n1_g   = (const float*)d_in[3];
    const float* n1_b   = (const float*)d_in[4];
    const float* sr_w   = (const float*)d_in[5];
    const float* sr_b   = (const float*)d_in[6];
    const float* an_g   = (const float*)d_in[7];
    const float* an_b   = (const float*)d_in[8];
    const float* qkv_w  = (const float*)d_in[9];
    const float* proj_w = (const float*)d_in[10];
    const float* proj_b = (const float*)d_in[11];
    const float* n2_g   = (const float*)d_in[12];
    const float* n2_b   = (const float*)d_in[13];
    const float* fc1_w  = (const float*)d_in[14];
    const float* fc1_b  = (const float*)d_in[15];
    const float* dw_w   = (const float*)d_in[16];
    const float* dw_b   = (const float*)d_in[17];
    const float* fc2_w  = (const float*)d_in[18];
    const float* fc2_b  = (const float*)d_in[19];
    const float* ca_w1  = (const float*)d_in[20];
    const float* ca_w2  = (const float*)d_in[21];
    const float* sp_w   = (const float*)d_in[22];
    const float* sp_b   = (const float*)d_in[23];
    float* out = (float*)d_out;

    float *p_xn, *p_ctx, *p_ctxp, *p_x1, *p_x2;
    bf16  *p_xa, *p_qkv, *p_attn, *p_hid, *p_hid2;
    float *p_pavg, *p_pmx, *p_avg, *p_mx, *p_ca, *p_smean, *p_smax, *p_sa;
    cudaGetSymbolAddress((void**)&p_xn,   g_xn);
    cudaGetSymbolAddress((void**)&p_xa,   g_xa);
    cudaGetSymbolAddress((void**)&p_qkv,  g_qkv);
    cudaGetSymbolAddress((void**)&p_ctx,  g_ctx);
    cudaGetSymbolAddress((void**)&p_ctxp, g_ctxp);
    cudaGetSymbolAddress((void**)&p_attn, g_attn);
    cudaGetSymbolAddress((void**)&p_x1,   g_x1);
    cudaGetSymbolAddress((void**)&p_x2,   g_x2);
    cudaGetSymbolAddress((void**)&p_hid,  g_hid);
    cudaGetSymbolAddress((void**)&p_hid2, g_hid2);
    cudaGetSymbolAddress((void**)&p_pavg, g_pavg);
    cudaGetSymbolAddress((void**)&p_pmx,  g_pmx);
    cudaGetSymbolAddress((void**)&p_avg,  g_avg);
    cudaGetSymbolAddress((void**)&p_mx,   g_mx);
    cudaGetSymbolAddress((void**)&p_ca,   g_ca);
    cudaGetSymbolAddress((void**)&p_smean,g_smean);
    cudaGetSymbolAddress((void**)&p_smax, g_smax);
    cudaGetSymbolAddress((void**)&p_sa,   g_sa);

    // ---- attention branch ----
    ln_kernel<float><<<MTOT, 256>>>(x, n1_g, n1_b, p_xn);
    attn_pre_kernel<<<MTOT, 256>>>(p_xn, sr_w, sr_b, an_g, an_b, p_xa);
    gemm_bf<bf16, bf16><<<dim3(768/128, MTOT/128), 256>>>(p_xa, qkv_w, p_qkv,
                                                MTOT, 768, 256, nullptr, nullptr, nullptr);
    qstat_partial_kernel<<<dim3(64, BB), 256>>>(p_qkv, p_pavg, p_pmx);
    qstat_final_kernel<<<BB, 256>>>(p_pavg, p_pmx, p_avg, p_mx);
    ctx_kernel<<<dim3(BB*NHEAD, 4), 1024>>>(p_qkv, p_ctxp);
    ctx_combine_kernel<<<(BB*NHEAD*1024)/256, 256>>>(p_ctxp, p_ctx);
    attn_apply_kernel<<<MTOT/16, 256>>>(p_qkv, p_ctx, p_avg, p_mx, p_attn);
    gemm_bf<bf16, float><<<dim3(256/128, MTOT/128), 256>>>(p_attn, proj_w, p_x1,
                                                MTOT, 256, 256, proj_b, p_xn, x);

    // ---- MixFFN ----
    ln_kernel<bf16><<<MTOT, 256>>>(p_x1, n2_g, n2_b, p_xa);   // reuse g_xa
    gemm_bf<bf16, bf16><<<dim3(1024/128, MTOT/128), 256>>>(p_xa, fc1_w, p_hid,
                                                 MTOT, 1024, 256, fc1_b, nullptr, nullptr);
    hid_conv_kernel<<<BB*HH, 256>>>(p_hid, dw_w, dw_b, p_hid2);
    gemm_bf<bf16, float><<<dim3(256/128, MTOT/128), 256>>>(p_hid2, fc2_w, p_x2,
                                                MTOT, 256, 1024, fc2_b, p_x1, nullptr);

    // ---- CSDA (CBAM) ----
    pool_partial_kernel<<<dim3(BB, 64), 256>>>(p_x2, p_pavg, p_pmx);
    pool_final_kernel<<<BB, 256>>>(p_pavg, p_pmx, p_avg, p_mx);
    ca_mlp_kernel<<<BB, 256>>>(p_avg, p_mx, ca_w1, ca_w2, p_ca);
    smap_kernel<<<MTOT, 256>>>(p_x2, p_ca, p_smean, p_smax);
    sp_conv_kernel<<<MTOT/256, 256>>>(p_smean, p_smax, sp_w, sp_b, p_sa);
    final_kernel<<<(MTOT*CH)/256, 256>>>(p_x2, p_ca, p_sa, out);
}

// round 16
// speedup vs baseline: 3.0690x; 1.0851x over previous
#include <cuda_runtime.h>
#include <cuda_bf16.h>
#include <math.h>

#define BB    16
#define NT    4096
#define CH    256
#define NHEAD 8
#define DH    32
#define HID   1024
#define HH    64
#define WW2   64
#define MTOT  (BB*NT)   // 65536

typedef __nv_bfloat16  bf16;
typedef __nv_bfloat162 bf162;

// ---------------- scratch ----------------------------------------------------
__device__ float g_xn  [MTOT*CH];
__device__ bf16  g_xa  [MTOT*CH];
__device__ bf16  g_qkv [MTOT*3*CH];
__device__ float g_ctx [BB*NHEAD*DH*DH];
__device__ float g_ctxp[4*BB*NHEAD*DH*DH];
__device__ bf16  g_attn[MTOT*CH];
__device__ float g_x1  [MTOT*CH];
__device__ float g_x2  [MTOT*CH];
__device__ bf16  g_hid [(size_t)MTOT*HID];
__device__ bf16  g_hid2[(size_t)MTOT*HID];
__device__ float g_pavg[BB*64*CH];
__device__ float g_pmx [BB*64*CH];
__device__ float g_avg [BB*CH];
__device__ float g_mx  [BB*CH];
__device__ float g_ca  [BB*CH];
__device__ float g_smean[MTOT];
__device__ float g_smax [MTOT];
__device__ float g_sa   [MTOT];
// bf16 weight copies (converted once per launch)
__device__ bf16  g_wqkv[3*CH*CH];
__device__ bf16  g_wproj[CH*CH];
__device__ bf16  g_wfc1[HID*CH];
__device__ bf16  g_wfc2[CH*HID];

__device__ __forceinline__ float geluf(float x) {
    return 0.5f * x * (1.f + erff(x * 0.70710678118654752f));
}
__device__ __forceinline__ float sigmoidf_(float x) {
    return 1.f / (1.f + expf(-x));
}
__device__ __forceinline__ void mma16(float* c, const unsigned* a, const unsigned* b) {
    asm("mma.sync.aligned.m16n8k16.row.col.f32.bf16.bf16.f32 "
        "{%0,%1,%2,%3},{%4,%5,%6,%7},{%8,%9},{%0,%1,%2,%3};"
        : "+f"(c[0]), "+f"(c[1]), "+f"(c[2]), "+f"(c[3])
        : "r"(a[0]), "r"(a[1]), "r"(a[2]), "r"(a[3]), "r"(b[0]), "r"(b[1]));
}
__device__ __forceinline__ void cpa16(void* smem_dst, const void* gmem_src) {
    unsigned s = (unsigned)__cvta_generic_to_shared(smem_dst);
    asm volatile("cp.async.cg.shared.global [%0], [%1], 16;\n" :: "r"(s), "l"(gmem_src));
}
__device__ __forceinline__ void cpa_commit() {
    asm volatile("cp.async.commit_group;\n" ::: "memory");
}
template<int N>
__device__ __forceinline__ void cpa_wait() {
    asm volatile("cp.async.wait_group %0;\n" :: "n"(N) : "memory");
}
// block reduce (256 thr): sum of two values via shuffle + 1 sync
__device__ __forceinline__ void blk_reduce2(float& s, float& sq, float* ws, float* wq) {
    #pragma unroll
    for (int o = 16; o > 0; o >>= 1) {
        s  += __shfl_xor_sync(0xffffffffu, s,  o);
        sq += __shfl_xor_sync(0xffffffffu, sq, o);
    }
    int warp = threadIdx.x >> 5, lane = threadIdx.x & 31;
    if (lane == 0) { ws[warp] = s; wq[warp] = sq; }
    __syncthreads();
    float ts = 0.f, tq = 0.f;
    #pragma unroll
    for (int i = 0; i < 8; i++) { ts += ws[i]; tq += wq[i]; }
    s = ts; sq = tq;
}

// ---------------- fp32 -> bf16 weight convert (float4 granularity) -----------
__global__ __launch_bounds__(256) void cvt_kernel(
    const float* __restrict__ w, bf16* __restrict__ o, int n4)
{
    int i = blockIdx.x*256 + threadIdx.x;
    if (i < n4) {
        float4 v = ((const float4*)w)[i];
        bf162 p0 = __floats2bfloat162_rn(v.x, v.y);
        bf162 p1 = __floats2bfloat162_rn(v.z, v.w);
        uint2 u;
        u.x = *reinterpret_cast<unsigned*>(&p0);
        u.y = *reinterpret_cast<unsigned*>(&p1);
        ((uint2*)o)[i] = u;
    }
}

// ---------------- LayerNorm over CH per row (templated output) ---------------
template<typename TO>
__global__ __launch_bounds__(256) void ln_kernel(
    const float* __restrict__ x, const float* __restrict__ g,
    const float* __restrict__ b, TO* __restrict__ out)
{
    int m = blockIdx.x;
    int c = threadIdx.x;
    __shared__ float ws[8], wq[8];
    float v = x[(size_t)m*CH + c];
    float s = v, sq = v*v;
    blk_reduce2(s, sq, ws, wq);
    float mean = s * (1.f/CH);
    float var  = sq * (1.f/CH) - mean*mean;
    float r = (v - mean) * rsqrtf(var + 1e-5f) * g[c] + b[c];
    if constexpr (sizeof(TO) == 4) out[(size_t)m*CH + c] = r;
    else                           out[(size_t)m*CH + c] = __float2bfloat16(r);
}

// ---------------- dwconv3x3(xn) -> LN -> gelu -> + xn  => xa (bf16) ---------
__global__ __launch_bounds__(256) void attn_pre_kernel(
    const float* __restrict__ xn, const float* __restrict__ sr_w,
    const float* __restrict__ sr_b, const float* __restrict__ an_g,
    const float* __restrict__ an_b, bf16* __restrict__ xa)
{
    int m = blockIdx.x;
    int b = m >> 12, n = m & 4095;
    int hh = n >> 6, ww = n & 63;
    int c = threadIdx.x;
    __shared__ float ws[8], wq[8];
    float acc = sr_b[c];
    #pragma unroll
    for (int dy = -1; dy <= 1; dy++) {
        int y = hh + dy; if (y < 0 || y >= HH) continue;
        #pragma unroll
        for (int dx = -1; dx <= 1; dx++) {
            int xx = ww + dx; if (xx < 0 || xx >= WW2) continue;
            acc += xn[((size_t)((b<<12) + (y<<6) + xx))*CH + c] *
                   sr_w[c*9 + (dy+1)*3 + (dx+1)];
        }
    }
    float s = acc, sq = acc*acc;
    blk_reduce2(s, sq, ws, wq);
    float mean = s * (1.f/CH);
    float var  = sq * (1.f/CH) - mean*mean;
    float nv = (acc - mean) * rsqrtf(var + 1e-5f) * an_g[c] + an_b[c];
    xa[(size_t)m*CH + c] = __float2bfloat16(xn[(size_t)m*CH + c] + geluf(nv));
}

// ---------------- bf16 tensor-core NT GEMM, cp.async 2-stage pipeline --------
// C[M,N] = A[M,K] * B[N,K]^T (+bias +add1 +add2). A,B bf16. M,N%128==0, K%32==0.
template<typename TO>
__global__ __launch_bounds__(256, 2) void gemm_bf(
    const bf16* __restrict__ A, const bf16* __restrict__ Bw,
    TO* __restrict__ Cc, int M, int N, int K,
    const float* __restrict__ bias, const float* __restrict__ add1,
    const float* __restrict__ add2)
{
    __shared__ unsigned As[2][128][20];   // [stage][row][packed-k pair], pad->20
    __shared__ unsigned Bs[2][128][20];
    int bm = blockIdx.y * 128, bn = blockIdx.x * 128;
    int tid = threadIdx.x;
    int warp = tid >> 5, lane = tid & 31;
    int wm = (warp & 1) * 64, wn = (warp >> 1) * 32;
    int g = lane >> 2, q = lane & 3;

    float acc[4][4][4];
    #pragma unroll
    for (int i = 0; i < 4; i++)
        #pragma unroll
        for (int j = 0; j < 4; j++)
            #pragma unroll
            for (int r = 0; r < 4; r++) acc[i][j][r] = 0.f;

    int lrow = tid >> 2;       // 0..63
    int lch  = tid & 3;        // 16B chunk within 32-elem row (4 chunks)

#define ISSUE_TILE(STAGE, K0)                                                  \
    _Pragma("unroll")                                                          \
    for (int i = 0; i < 2; i++) {                                              \
        int row = lrow + i*64;                                                 \
        cpa16(&As[STAGE][row][lch*4], &A [(size_t)(bm+row)*K + (K0) + lch*8]); \
        cpa16(&Bs[STAGE][row][lch*4], &Bw[(size_t)(bn+row)*K + (K0) + lch*8]); \
    }

    int KT = K >> 5;           // number of 32-wide k-tiles
    ISSUE_TILE(0, 0)
    cpa_commit();
    for (int kt = 0; kt < KT; kt++) {
        if (kt + 1 < KT) {
            ISSUE_TILE((kt+1)&1, (kt+1)*32)
            cpa_commit();
            cpa_wait<1>();
        } else {
            cpa_wait<0>();
        }
        __syncthreads();
        int st = kt & 1;
        #pragma unroll
        for (int ks = 0; ks < 2; ks++) {
            int kb = ks*8;
            unsigned af[4][4], bfr[4][2];
            #pragma unroll
            for (int mt = 0; mt < 4; mt++) {
                int row = wm + mt*16 + g;
                af[mt][0] = As[st][row  ][kb+q];
                af[mt][1] = As[st][row+8][kb+q];
                af[mt][2] = As[st][row  ][kb+q+4];
                af[mt][3] = As[st][row+8][kb+q+4];
            }
            #pragma unroll
            for (int nt = 0; nt < 4; nt++) {
                int col = wn + nt*8 + g;
                bfr[nt][0] = Bs[st][col][kb+q];
                bfr[nt][1] = Bs[st][col][kb+q+4];
            }
            #pragma unroll
            for (int mt = 0; mt < 4; mt++)
                #pragma unroll
                for (int nt = 0; nt < 4; nt++)
                    mma16(acc[mt][nt], af[mt], bfr[nt]);
        }
        __syncthreads();
    }
#undef ISSUE_TILE

    #pragma unroll
    for (int mt = 0; mt < 4; mt++) {
        #pragma unroll
        for (int half = 0; half < 2; half++) {
            int r = bm + wm + mt*16 + g + half*8;
            #pragma unroll
            for (int nt = 0; nt < 4; nt++) {
                int c0 = bn + wn + nt*8 + q*2;
                float v0 = acc[mt][nt][half*2+0];
                float v1 = acc[mt][nt][half*2+1];
                if (bias) { v0 += bias[c0]; v1 += bias[c0+1]; }
                size_t idx = (size_t)r*N + c0;
                if (add1) { float2 t = *(const float2*)&add1[idx]; v0 += t.x; v1 += t.y; }
                if (add2) { float2 t = *(const float2*)&add2[idx]; v0 += t.x; v1 += t.y; }
                if constexpr (sizeof(TO) == 4) {
                    float2 o; o.x = v0; o.y = v1;
                    *(float2*)&Cc[idx] = o;
                } else {
                    bf162 o = __floats2bfloat162_rn(v0, v1);
                    *(bf162*)&Cc[idx] = o;
                }
            }
        }
    }
}

// ---------------- q column-softmax stats: partial (64 chunks of 64 rows) -----
__global__ __launch_bounds__(256) void qstat_partial_kernel(
    const bf16* __restrict__ qkv, float* __restrict__ pm, float* __restrict__ ps)
{
    int chunk = blockIdx.x, b = blockIdx.y;
    int c = threadIdx.x;
    float m = -3.0e38f, s = 0.f;
    size_t base = ((size_t)(b*NT + chunk*64))*768 + c;
    for (int r = 0; r < 64; r++) {
        float v = __bfloat162float(qkv[base + (size_t)r*768]);
        float nm = fmaxf(m, v);
        s = s*expf(m - nm) + expf(v - nm);
        m = nm;
    }
    pm[(b*64 + chunk)*CH + c] = m;
    ps[(b*64 + chunk)*CH + c] = s;
}

__global__ __launch_bounds__(256) void qstat_final_kernel(
    const float* __restrict__ pm, const float* __restrict__ ps,
    float* __restrict__ qm, float* __restrict__ qinv)
{
    int b = blockIdx.x;
    int c = threadIdx.x;
    float M = -3.0e38f;
    for (int s = 0; s < 64; s++) M = fmaxf(M, pm[(b*64 + s)*CH + c]);
    float S = 0.f;
    for (int s = 0; s < 64; s++) S += ps[(b*64 + s)*CH + c] * expf(pm[(b*64 + s)*CH + c] - M);
    qm[b*CH + c] = M;
    qinv[b*CH + c] = 1.f / S;
}

// ---------------- ctx partial: 4-way split over tokens -----------------------
__global__ __launch_bounds__(1024) void ctx_kernel(
    const bf16* __restrict__ qkv, float* __restrict__ ctxp)
{
    int bh = blockIdx.x;               // b*8+h
    int split = blockIdx.y;            // 0..3
    int b = bh >> 3, h = bh & 7;
    __shared__ float ks[32][33];
    __shared__ float vs[32][33];
    int tid = threadIdx.x;
    int d = tid & 31, e = tid >> 5;
    int lrow = tid >> 5, lane = tid & 31;
    float acc = 0.f;
    for (int n0 = split*1024; n0 < (split+1)*1024; n0 += 32) {
        size_t rbase = ((size_t)(b*NT + n0 + lrow))*768 + h*32 + lane;
        float kv = __bfloat162float(qkv[rbase + 256]);
        float mx = kv;
        #pragma unroll
        for (int o = 16; o > 0; o >>= 1) mx = fmaxf(mx, __shfl_xor_sync(0xffffffffu, mx, o));
        float ek = expf(kv - mx);
        float sk = ek;
        #pragma unroll
        for (int o = 16; o > 0; o >>= 1) sk += __shfl_xor_sync(0xffffffffu, sk, o);
        ks[lrow][lane] = ek / sk;
        vs[lrow][lane] = __bfloat162float(qkv[rbase + 512]);
        __syncthreads();
        #pragma unroll
        for (int r = 0; r < 32; r++) acc += ks[r][d] * vs[r][e];
        __syncthreads();
    }
    ctxp[((size_t)split*BB*NHEAD + bh)*1024 + d*32 + e] = acc;
}

__global__ __launch_bounds__(256) void ctx_combine_kernel(
    const float* __restrict__ ctxp, float* __restrict__ ctx)
{
    int i = blockIdx.x*256 + threadIdx.x;
    const int STRIDE = BB*NHEAD*1024;
    ctx[i] = ctxp[i] + ctxp[STRIDE + i] + ctxp[2*STRIDE + i] + ctxp[3*STRIDE + i];
}

// ---------------- attn[b,n,c=h*32+e] = sum_d softmaxed q * ctx ---------------
__global__ __launch_bounds__(256) void attn_apply_kernel(
    const bf16* __restrict__ qkv, const float* __restrict__ ctx,
    const float* __restrict__ qm, const float* __restrict__ qinv,
    bf16* __restrict__ attn)
{
    int blk = blockIdx.x;
    int b = blk >> 8;
    __shared__ float ctx_s[NHEAD*DH*DH];
    __shared__ float qrow[256];
    __shared__ float qm_s[256], qi_s[256];
    int c = threadIdx.x;
    for (int i = threadIdx.x; i < NHEAD*DH*DH; i += 256)
        ctx_s[i] = ctx[(size_t)b*NHEAD*DH*DH + i];
    qm_s[c] = qm[b*CH + c];
    qi_s[c] = qinv[b*CH + c];
    int h = c >> 5, e = c & 31;
    for (int r = 0; r < 16; r++) {
        int m = blk*16 + r;
        __syncthreads();
        qrow[c] = expf(__bfloat162float(qkv[(size_t)m*768 + c]) - qm_s[c]) * qi_s[c];
        __syncthreads();
        float s = 0.f;
        #pragma unroll
        for (int d2 = 0; d2 < 32; d2++)
            s += qrow[h*32 + d2] * ctx_s[(h*32 + d2)*32 + e];
        attn[(size_t)m*CH + c] = __float2bfloat16(s);
    }
}

// ---------------- hidden dwconv3x3 + gelu: rolling-window over x -------------
__global__ __launch_bounds__(256) void hid_conv_kernel(
    const bf16* __restrict__ hid, const float* __restrict__ dw_w,
    const float* __restrict__ dw_b, bf16* __restrict__ hid2)
{
    int blk = blockIdx.x;              // b*64 + y
    int b = blk >> 6, y = blk & 63;
    int c4 = threadIdx.x * 4;
    float w[4][9];
    #pragma unroll
    for (int i = 0; i < 4; i++)
        #pragma unroll
        for (int k = 0; k < 9; k++) w[i][k] = __ldg(&dw_w[(c4+i)*9 + k]);
    float bs0 = dw_b[c4+0], bs1 = dw_b[c4+1], bs2 = dw_b[c4+2], bs3 = dw_b[c4+3];

    float win[3][3][4];
    #pragma unroll
    for (int cc = 0; cc < 3; cc++)
        #pragma unroll
        for (int r = 0; r < 3; r++)
            #pragma unroll
            for (int ch = 0; ch < 4; ch++) win[cc][r][ch] = 0.f;

    #pragma unroll
    for (int r = 0; r < 3; r++) {
        int yy = y - 1 + r;
        if (yy >= 0 && yy < HH) {
            uint2 u = *(const uint2*)&hid[((size_t)((b<<12) + (yy<<6)))*HID + c4];
            bf162 h01 = *reinterpret_cast<bf162*>(&u.x);
            bf162 h23 = *reinterpret_cast<bf162*>(&u.y);
            win[1][r][0] = __bfloat162float(h01.x); win[1][r][1] = __bfloat162float(h01.y);
            win[1][r][2] = __bfloat162float(h23.x); win[1][r][3] = __bfloat162float(h23.y);
        }
    }
    for (int x = 0; x < 64; x++) {
        #pragma unroll
        for (int r = 0; r < 3; r++) {
            int yy = y - 1 + r;
            if (x + 1 < 64 && yy >= 0 && yy < HH) {
                uint2 u = *(const uint2*)&hid[((size_t)((b<<12) + (yy<<6) + x + 1))*HID + c4];
                bf162 h01 = *reinterpret_cast<bf162*>(&u.x);
                bf162 h23 = *reinterpret_cast<bf162*>(&u.y);
                win[2][r][0] = __bfloat162float(h01.x); win[2][r][1] = __bfloat162float(h01.y);
                win[2][r][2] = __bfloat162float(h23.x); win[2][r][3] = __bfloat162float(h23.y);
            } else {
                win[2][r][0] = win[2][r][1] = win[2][r][2] = win[2][r][3] = 0.f;
            }
        }
        float a0 = bs0, a1 = bs1, a2 = bs2, a3 = bs3;
        #pragma unroll
        for (int r = 0; r < 3; r++)
            #pragma unroll
            for (int col = 0; col < 3; col++) {
                float w0 = w[0][r*3+col], w1 = w[1][r*3+col];
                float w2 = w[2][r*3+col], w3 = w[3][r*3+col];
                a0 += win[col][r][0]*w0;
                a1 += win[col][r][1]*w1;
                a2 += win[col][r][2]*w2;
                a3 += win[col][r][3]*w3;
            }
        bf162 o01 = __floats2bfloat162_rn(geluf(a0), geluf(a1));
        bf162 o23 = __floats2bfloat162_rn(geluf(a2), geluf(a3));
        uint2 o; o.x = *reinterpret_cast<unsigned*>(&o01); o.y = *reinterpret_cast<unsigned*>(&o23);
        *(uint2*)&hid2[((size_t)((b<<12) + (y<<6) + x))*HID + c4] = o;
        #pragma unroll
        for (int r = 0; r < 3; r++)
            #pragma unroll
            for (int ch = 0; ch < 4; ch++) {
                win[0][r][ch] = win[1][r][ch];
                win[1][r][ch] = win[2][r][ch];
            }
    }
}

// ---------------- CBAM: partial channel pool (64 chunks of 64 tokens) --------
__global__ __launch_bounds__(256) void pool_partial_kernel(
    const float* __restrict__ x2, float* __restrict__ pavg, float* __restrict__ pmx)
{
    int b = blockIdx.x, s = blockIdx.y;
    int c = threadIdx.x;
    float sum = 0.f, mx = -3.0e38f;
    for (int n = s*64; n < (s+1)*64; n++) {
        float v = x2[((size_t)(b*NT + n))*CH + c];
        sum += v; mx = fmaxf(mx, v);
    }
    pavg[(b*64 + s)*CH + c] = sum;
    pmx [(b*64 + s)*CH + c] = mx;
}

__global__ __launch_bounds__(256) void pool_final_kernel(
    const float* __restrict__ pavg, const float* __restrict__ pmx,
    float* __restrict__ avg, float* __restrict__ mx)
{
    int b = blockIdx.x;
    int c = threadIdx.x;
    float sum = 0.f, m = -3.0e38f;
    for (int s = 0; s < 64; s++) {
        sum += pavg[(b*64 + s)*CH + c];
        m = fmaxf(m, pmx[(b*64 + s)*CH + c]);
    }
    avg[b*CH + c] = sum * (1.f/NT);
    mx [b*CH + c] = m;
}

// ---------------- CBAM: channel-attention MLP --------------------------------
__global__ __launch_bounds__(256) void ca_mlp_kernel(
    const float* __restrict__ avg, const float* __restrict__ mxp,
    const float* __restrict__ w1, const float* __restrict__ w2,
    float* __restrict__ ca)
{
    int b = blockIdx.x;
    int c = threadIdx.x;
    __shared__ float sa_[256], sm_[256], t[32];
    sa_[c] = avg[b*CH + c];
    sm_[c] = mxp[b*CH + c];
    __syncthreads();
    if (c < 32) {
        int r = c & 15;
        const float* src = (c < 16) ? sa_ : sm_;
        float s = 0.f;
        for (int k = 0; k < 256; k++) s += src[k] * w1[r*256 + k];
        t[c] = fmaxf(s, 0.f);
    }
    __syncthreads();
    float s = 0.f;
    #pragma unroll
    for (int r = 0; r < 16; r++) s += (t[r] + t[16 + r]) * w2[c*16 + r];
    ca[b*CH + c] = sigmoidf_(s);
}

// ---------------- CBAM: spatial map ------------------------------------------
__global__ __launch_bounds__(256) void smap_kernel(
    const float* __restrict__ x2, const float* __restrict__ ca,
    float* __restrict__ smean, float* __restrict__ smax)
{
    int m = blockIdx.x;
    int b = m >> 12;
    int c = threadIdx.x;
    __shared__ float ws[8], wq[8];
    float v = x2[(size_t)m*CH + c] * ca[b*CH + c];
    float s = v;
    float mxv = v;
    #pragma unroll
    for (int o = 16; o > 0; o >>= 1) {
        s   += __shfl_xor_sync(0xffffffffu, s, o);
        mxv  = fmaxf(mxv, __shfl_xor_sync(0xffffffffu, mxv, o));
    }
    int warp = threadIdx.x >> 5, lane = threadIdx.x & 31;
    if (lane == 0) { ws[warp] = s; wq[warp] = mxv; }
    __syncthreads();
    if (threadIdx.x == 0) {
        float ts = 0.f, tm = -3.0e38f;
        #pragma unroll
        for (int i = 0; i < 8; i++) { ts += ws[i]; tm = fmaxf(tm, wq[i]); }
        smean[m] = ts * (1.f/CH); smax[m] = tm;
    }
}

// ---------------- CBAM: 7x7 spatial conv + sigmoid ---------------------------
__global__ __launch_bounds__(256) void sp_conv_kernel(
    const float* __restrict__ smean, const float* __restrict__ smax,
    const float* __restrict__ sp_w, const float* __restrict__ sp_b,
    float* __restrict__ sa)
{
    int m = blockIdx.x*256 + threadIdx.x;
    int b = m >> 12, n = m & 4095;
    int hh = n >> 6, ww = n & 63;
    float acc = sp_b[0];
    #pragma unroll
    for (int dy = -3; dy <= 3; dy++) {
        int y = hh + dy; if (y < 0 || y >= HH) continue;
        #pragma unroll
        for (int dx = -3; dx <= 3; dx++) {
            int xx = ww + dx; if (xx < 0 || xx >= WW2) continue;
            int idx = (b << 12) + (y << 6) + xx;
            int k = (dy+3)*7 + (dx+3);
            acc += smean[idx]*sp_w[k] + smax[idx]*sp_w[49 + k];
        }
    }
    sa[m] = sigmoidf_(acc);
}

// ---------------- final scale ------------------------------------------------
__global__ __launch_bounds__(256) void final_kernel(
    const float* __restrict__ x2, const float* __restrict__ ca,
    const float* __restrict__ sa, float* __restrict__ out)
{
    int i = blockIdx.x*256 + threadIdx.x;
    int m = i >> 8, c = i & 255;
    int b = m >> 12;
    out[i] = x2[i] * ca[b*CH + c] * sa[m];
}

// ---------------- launch -----------------------------------------------------
extern "C" void kernel_launch(void* const* d_in, const int* in_sizes, int n_in,
                              void* d_out, int out_size)
{
    const float* x      = (const float*)d_in[0];
    const float* n1_g   = (const float*)d_in[3];
    const float* n1_b   = (const float*)d_in[4];
    const float* sr_w   = (const float*)d_in[5];
    const float* sr_b   = (const float*)d_in[6];
    const float* an_g   = (const float*)d_in[7];
    const float* an_b   = (const float*)d_in[8];
    const float* qkv_w  = (const float*)d_in[9];
    const float* proj_w = (const float*)d_in[10];
    const float* proj_b = (const float*)d_in[11];
    const float* n2_g   = (const float*)d_in[12];
    const float* n2_b   = (const float*)d_in[13];
    const float* fc1_w  = (const float*)d_in[14];
    const float* fc1_b  = (const float*)d_in[15];
    const float* dw_w   = (const float*)d_in[16];
    const float* dw_b   = (const float*)d_in[17];
    const float* fc2_w  = (const float*)d_in[18];
    const float* fc2_b  = (const float*)d_in[19];
    const float* ca_w1  = (const float*)d_in[20];
    const float* ca_w2  = (const float*)d_in[21];
    const float* sp_w   = (const float*)d_in[22];
    const float* sp_b   = (const float*)d_in[23];
    float* out = (float*)d_out;

    float *p_xn, *p_ctx, *p_ctxp, *p_x1, *p_x2;
    bf16  *p_xa, *p_qkv, *p_attn, *p_hid, *p_hid2;
    bf16  *p_wqkv, *p_wproj, *p_wfc1, *p_wfc2;
    float *p_pavg, *p_pmx, *p_avg, *p_mx, *p_ca, *p_smean, *p_smax, *p_sa;
    cudaGetSymbolAddress((void**)&p_xn,   g_xn);
    cudaGetSymbolAddress((void**)&p_xa,   g_xa);
    cudaGetSymbolAddress((void**)&p_qkv,  g_qkv);
    cudaGetSymbolAddress((void**)&p_ctx,  g_ctx);
    cudaGetSymbolAddress((void**)&p_ctxp, g_ctxp);
    cudaGetSymbolAddress((void**)&p_attn, g_attn);
    cudaGetSymbolAddress((void**)&p_x1,   g_x1);
    cudaGetSymbolAddress((void**)&p_x2,   g_x2);
    cudaGetSymbolAddress((void**)&p_hid,  g_hid);
    cudaGetSymbolAddress((void**)&p_hid2, g_hid2);
    cudaGetSymbolAddress((void**)&p_wqkv, g_wqkv);
    cudaGetSymbolAddress((void**)&p_wproj,g_wproj);
    cudaGetSymbolAddress((void**)&p_wfc1, g_wfc1);
    cudaGetSymbolAddress((void**)&p_wfc2, g_wfc2);
    cudaGetSymbolAddress((void**)&p_pavg, g_pavg);
    cudaGetSymbolAddress((void**)&p_pmx,  g_pmx);
    cudaGetSymbolAddress((void**)&p_avg,  g_avg);
    cudaGetSymbolAddress((void**)&p_mx,   g_mx);
    cudaGetSymbolAddress((void**)&p_ca,   g_ca);
    cudaGetSymbolAddress((void**)&p_smean,g_smean);
    cudaGetSymbolAddress((void**)&p_smax, g_smax);
    cudaGetSymbolAddress((void**)&p_sa,   g_sa);

    // ---- weight conversion (once per launch; graph-capturable) ----
    cvt_kernel<<<(3*CH*CH/4 + 255)/256, 256>>>(qkv_w,  p_wqkv,  3*CH*CH/4);
    cvt_kernel<<<(CH*CH/4   + 255)/256, 256>>>(proj_w, p_wproj, CH*CH/4);
    cvt_kernel<<<(HID*CH/4  + 255)/256, 256>>>(fc1_w,  p_wfc1,  HID*CH/4);
    cvt_kernel<<<(CH*HID/4  + 255)/256, 256>>>(fc2_w,  p_wfc2,  CH*HID/4);

    // ---- attention branch ----
    ln_kernel<float><<<MTOT, 256>>>(x, n1_g, n1_b, p_xn);
    attn_pre_kernel<<<MTOT, 256>>>(p_xn, sr_w, sr_b, an_g, an_b, p_xa);
    gemm_bf<bf16><<<dim3(768/128, MTOT/128), 256>>>(p_xa, p_wqkv, p_qkv,
                                                MTOT, 768, 256, nullptr, nullptr, nullptr);
    qstat_partial_kernel<<<dim3(64, BB), 256>>>(p_qkv, p_pavg, p_pmx);
    qstat_final_kernel<<<BB, 256>>>(p_pavg, p_pmx, p_avg, p_mx);
    ctx_kernel<<<dim3(BB*NHEAD, 4), 1024>>>(p_qkv, p_ctxp);
    ctx_combine_kernel<<<(BB*NHEAD*1024)/256, 256>>>(p_ctxp, p_ctx);
    attn_apply_kernel<<<MTOT/16, 256>>>(p_qkv, p_ctx, p_avg, p_mx, p_attn);
    gemm_bf<float><<<dim3(256/128, MTOT/128), 256>>>(p_attn, p_wproj, p_x1,
                                                MTOT, 256, 256, proj_b, p_xn, x);

    // ---- MixFFN ----
    ln_kernel<bf16><<<MTOT, 256>>>(p_x1, n2_g, n2_b, p_xa);
    gemm_bf<bf16><<<dim3(1024/128, MTOT/128), 256>>>(p_xa, p_wfc1, p_hid,
                                                 MTOT, 1024, 256, fc1_b, nullptr, nullptr);
    hid_conv_kernel<<<BB*HH, 256>>>(p_hid, dw_w, dw_b, p_hid2);
    gemm_bf<float><<<dim3(256/128, MTOT/128), 256>>>(p_hid2, p_wfc2, p_x2,
                                                MTOT, 256, 1024, fc2_b, p_x1, nullptr);

    // ---- CSDA (CBAM) ----
    pool_partial_kernel<<<dim3(BB, 64), 256>>>(p_x2, p_pavg, p_pmx);
    pool_final_kernel<<<BB, 256>>>(p_pavg, p_pmx, p_avg, p_mx);
    ca_mlp_kernel<<<BB, 256>>>(p_avg, p_mx, ca_w1, ca_w2, p_ca);
    smap_kernel<<<MTOT, 256>>>(p_x2, p_ca, p_smean, p_smax);
    sp_conv_kernel<<<MTOT/256, 256>>>(p_smean, p_smax, sp_w, sp_b, p_sa);
    final_kernel<<<(MTOT*CH)/256, 256>>>(p_x2, p_ca, p_sa, out);
}